// round 2
// baseline (speedup 1.0000x reference)
#include <cuda_runtime.h>
#include <cuda_bf16.h>
#include <cstdint>
#include <cstddef>

// Problem constants
#define Bq  4
#define Sq  2048
#define Dq  1024
#define Hq  16
#define HDq 64
#define Mq  (Bq * Sq)   // 8192

// Scratch: Q, K, V, attn-out in [B, S, D] layout (head h occupies cols h*64..h*64+63)
__device__ float g_q[(size_t)Mq * Dq];
__device__ float g_k[(size_t)Mq * Dq];
__device__ float g_v[(size_t)Mq * Dq];
__device__ float g_attn[(size_t)Mq * Dq];

// ---------------------------------------------------------------------------
// C[M,N] = A[M,K] @ W[N,K]^T   (both operands K-major, "NT" GEMM)
// 128x128 tile, BK=16, 256 threads, 8x8 per-thread microtile.
// ---------------------------------------------------------------------------
__global__ __launch_bounds__(256) void gemm_nt(
    const float* __restrict__ A, const float* __restrict__ W,
    float* __restrict__ C, int M, int N, int K)
{
    __shared__ float As[16][132];   // [k][m], padded
    __shared__ float Ws[16][132];   // [k][n], padded

    const int tid = threadIdx.x;
    const int tx = tid & 15;        // 0..15 -> n microtile
    const int ty = tid >> 4;        // 0..15 -> m microtile
    const int bm = blockIdx.y * 128;
    const int bn = blockIdx.x * 128;

    float acc[8][8];
    #pragma unroll
    for (int i = 0; i < 8; i++)
        #pragma unroll
        for (int j = 0; j < 8; j++) acc[i][j] = 0.f;

    for (int k0 = 0; k0 < K; k0 += 16) {
        #pragma unroll
        for (int i = 0; i < 2; i++) {
            int lin = tid + i * 256;
            int row = lin >> 2;            // 0..127
            int kk  = (lin & 3) << 2;      // 0,4,8,12
            float4 a = *(const float4*)(A + (size_t)(bm + row) * K + k0 + kk);
            As[kk + 0][row] = a.x; As[kk + 1][row] = a.y;
            As[kk + 2][row] = a.z; As[kk + 3][row] = a.w;
            float4 w = *(const float4*)(W + (size_t)(bn + row) * K + k0 + kk);
            Ws[kk + 0][row] = w.x; Ws[kk + 1][row] = w.y;
            Ws[kk + 2][row] = w.z; Ws[kk + 3][row] = w.w;
        }
        __syncthreads();

        #pragma unroll
        for (int k = 0; k < 16; k++) {
            float a[8], b[8];
            *(float4*)(a + 0) = *(const float4*)&As[k][ty * 8];
            *(float4*)(a + 4) = *(const float4*)&As[k][ty * 8 + 4];
            *(float4*)(b + 0) = *(const float4*)&Ws[k][tx * 8];
            *(float4*)(b + 4) = *(const float4*)&Ws[k][tx * 8 + 4];
            #pragma unroll
            for (int i = 0; i < 8; i++)
                #pragma unroll
                for (int j = 0; j < 8; j++)
                    acc[i][j] = fmaf(a[i], b[j], acc[i][j]);
        }
        __syncthreads();
    }

    #pragma unroll
    for (int i = 0; i < 8; i++) {
        float* cp = C + (size_t)(bm + ty * 8 + i) * N + bn + tx * 8;
        *(float4*)cp       = make_float4(acc[i][0], acc[i][1], acc[i][2], acc[i][3]);
        *(float4*)(cp + 4) = make_float4(acc[i][4], acc[i][5], acc[i][6], acc[i][7]);
    }
}

// ---------------------------------------------------------------------------
// Flash-style attention. One block = 64 query rows of one (b,h).
// Streams K/V in 64-row tiles; online softmax; masked entries contribute
// exactly 0 (matches reference: -1e9 additive mask underflows after softmax,
// then multiplicative re-mask zeroes them anyway).
// Mask is read as 32-bit words (bool promoted to int32/float32 by the
// harness); nonzero == keep, which is correct for both promotions.
// Thread layout: 16x16, each thread owns a 4x4 patch. Row reductions via
// __shfl_xor within the 16-lane tx-group.
// ---------------------------------------------------------------------------
#define PADK 68   // smem leading dim (floats)

__global__ __launch_bounds__(256) void attn_fused(
    const float* __restrict__ Q, const float* __restrict__ K,
    const float* __restrict__ V, const unsigned int* __restrict__ mask,
    float* __restrict__ O)
{
    extern __shared__ float sm[];
    float* Qs = sm;                  // [64][PADK]  row-major (q, hd)
    float* Kt = sm + 64 * PADK;      // [64][PADK]  transposed (hd, s)
    float* Vs = sm + 2 * 64 * PADK;  // [64][PADK]  row-major (s, hd)
    float* Ps = sm + 3 * 64 * PADK;  // [64][PADK]  row-major (q, s)

    const int tid = threadIdx.x;
    const int tx = tid & 15;
    const int ty = tid >> 4;
    const int bh = blockIdx.y;       // 0..63
    const int b  = bh >> 4;
    const int h  = bh & 15;
    const int q0 = blockIdx.x * 64;

    const float* Qg = Q + (size_t)b * Sq * Dq + (size_t)h * HDq;
    const float* Kg = K + (size_t)b * Sq * Dq + (size_t)h * HDq;
    const float* Vg = V + (size_t)b * Sq * Dq + (size_t)h * HDq;
    const unsigned int* Mg = mask + (size_t)b * Sq * Sq;

    // Load Q tile (straight copy, rows are 64 contiguous floats)
    #pragma unroll
    for (int i = 0; i < 4; i++) {
        int lin = tid + i * 256;
        int r = lin >> 4;
        int c = (lin & 15) << 2;
        *(float4*)&Qs[r * PADK + c] = *(const float4*)(Qg + (size_t)(q0 + r) * Dq + c);
    }

    float m_i[4], l_i[4], acc[4][4];
    #pragma unroll
    for (int i = 0; i < 4; i++) {
        m_i[i] = -1e30f; l_i[i] = 0.f;
        #pragma unroll
        for (int j = 0; j < 4; j++) acc[i][j] = 0.f;
    }

    for (int kb = 0; kb < Sq; kb += 64) {
        __syncthreads();   // protect Kt/Vs/Ps reuse (and first-iter Qs visibility)

        // Load K (transposed into Kt) and V (row-major)
        #pragma unroll
        for (int i = 0; i < 4; i++) {
            int lin = tid + i * 256;
            int r = lin >> 4;
            int c = (lin & 15) << 2;
            float4 kv = *(const float4*)(Kg + (size_t)(kb + r) * Dq + c);
            Kt[(c + 0) * PADK + r] = kv.x;
            Kt[(c + 1) * PADK + r] = kv.y;
            Kt[(c + 2) * PADK + r] = kv.z;
            Kt[(c + 3) * PADK + r] = kv.w;
            *(float4*)&Vs[r * PADK + c] = *(const float4*)(Vg + (size_t)(kb + r) * Dq + c);
        }
        __syncthreads();

        // GEMM1: s = Q @ K^T  (a-reads broadcast across tx-group; b-reads float4)
        float s[4][4];
        #pragma unroll
        for (int i = 0; i < 4; i++)
            #pragma unroll
            for (int j = 0; j < 4; j++) s[i][j] = 0.f;

        #pragma unroll 8
        for (int k = 0; k < 64; k++) {
            float4 bv = *(const float4*)&Kt[k * PADK + tx * 4];
            float a0 = Qs[(ty * 4 + 0) * PADK + k];
            float a1 = Qs[(ty * 4 + 1) * PADK + k];
            float a2 = Qs[(ty * 4 + 2) * PADK + k];
            float a3 = Qs[(ty * 4 + 3) * PADK + k];
            s[0][0] = fmaf(a0, bv.x, s[0][0]); s[0][1] = fmaf(a0, bv.y, s[0][1]);
            s[0][2] = fmaf(a0, bv.z, s[0][2]); s[0][3] = fmaf(a0, bv.w, s[0][3]);
            s[1][0] = fmaf(a1, bv.x, s[1][0]); s[1][1] = fmaf(a1, bv.y, s[1][1]);
            s[1][2] = fmaf(a1, bv.z, s[1][2]); s[1][3] = fmaf(a1, bv.w, s[1][3]);
            s[2][0] = fmaf(a2, bv.x, s[2][0]); s[2][1] = fmaf(a2, bv.y, s[2][1]);
            s[2][2] = fmaf(a2, bv.z, s[2][2]); s[2][3] = fmaf(a2, bv.w, s[2][3]);
            s[3][0] = fmaf(a3, bv.x, s[3][0]); s[3][1] = fmaf(a3, bv.y, s[3][1]);
            s[3][2] = fmaf(a3, bv.z, s[3][2]); s[3][3] = fmaf(a3, bv.w, s[3][3]);
        }

        // Mask + online softmax update
        #pragma unroll
        for (int i = 0; i < 4; i++) {
            const uint4 mv = *(const uint4*)(Mg + (size_t)(q0 + ty * 4 + i) * Sq + kb + tx * 4);
            const bool mk[4] = {mv.x != 0u, mv.y != 0u, mv.z != 0u, mv.w != 0u};
            float rmax = -1e30f;
            #pragma unroll
            for (int j = 0; j < 4; j++) {
                s[i][j] *= 0.125f;                 // 1/sqrt(64)
                if (!mk[j]) s[i][j] = -1e30f;
                rmax = fmaxf(rmax, s[i][j]);
            }
            #pragma unroll
            for (int o = 8; o >= 1; o >>= 1)
                rmax = fmaxf(rmax, __shfl_xor_sync(0xffffffffu, rmax, o));

            float mnew = fmaxf(m_i[i], rmax);
            float p[4]; float rsum = 0.f;
            #pragma unroll
            for (int j = 0; j < 4; j++) {
                p[j] = mk[j] ? __expf(s[i][j] - mnew) : 0.f;
                rsum += p[j];
            }
            *(float4*)&Ps[(ty * 4 + i) * PADK + tx * 4] = make_float4(p[0], p[1], p[2], p[3]);
            #pragma unroll
            for (int o = 8; o >= 1; o >>= 1)
                rsum += __shfl_xor_sync(0xffffffffu, rsum, o);

            float alpha = __expf(m_i[i] - mnew);   // exp(0)=1 when both -1e30
            l_i[i] = l_i[i] * alpha + rsum;
            m_i[i] = mnew;
            #pragma unroll
            for (int j = 0; j < 4; j++) acc[i][j] *= alpha;
        }
        __syncthreads();   // Ps fully written before GEMM2

        // GEMM2: acc += P @ V  (a-reads broadcast; b-reads float4)
        #pragma unroll 8
        for (int k = 0; k < 64; k++) {
            float4 bv = *(const float4*)&Vs[k * PADK + tx * 4];
            float a0 = Ps[(ty * 4 + 0) * PADK + k];
            float a1 = Ps[(ty * 4 + 1) * PADK + k];
            float a2 = Ps[(ty * 4 + 2) * PADK + k];
            float a3 = Ps[(ty * 4 + 3) * PADK + k];
            acc[0][0] = fmaf(a0, bv.x, acc[0][0]); acc[0][1] = fmaf(a0, bv.y, acc[0][1]);
            acc[0][2] = fmaf(a0, bv.z, acc[0][2]); acc[0][3] = fmaf(a0, bv.w, acc[0][3]);
            acc[1][0] = fmaf(a1, bv.x, acc[1][0]); acc[1][1] = fmaf(a1, bv.y, acc[1][1]);
            acc[1][2] = fmaf(a1, bv.z, acc[1][2]); acc[1][3] = fmaf(a1, bv.w, acc[1][3]);
            acc[2][0] = fmaf(a2, bv.x, acc[2][0]); acc[2][1] = fmaf(a2, bv.y, acc[2][1]);
            acc[2][2] = fmaf(a2, bv.z, acc[2][2]); acc[2][3] = fmaf(a2, bv.w, acc[2][3]);
            acc[3][0] = fmaf(a3, bv.x, acc[3][0]); acc[3][1] = fmaf(a3, bv.y, acc[3][1]);
            acc[3][2] = fmaf(a3, bv.z, acc[3][2]); acc[3][3] = fmaf(a3, bv.w, acc[3][3]);
        }
    }

    // Epilogue: normalize and store
    float* Og = O + (size_t)b * Sq * Dq + (size_t)h * HDq;
    #pragma unroll
    for (int i = 0; i < 4; i++) {
        float inv = l_i[i] > 0.f ? 1.f / l_i[i] : 0.f;
        *(float4*)(Og + (size_t)(q0 + ty * 4 + i) * Dq + tx * 4) =
            make_float4(acc[i][0] * inv, acc[i][1] * inv, acc[i][2] * inv, acc[i][3] * inv);
    }
}

// ---------------------------------------------------------------------------
// Launch: 3 projection GEMMs -> fused attention -> output GEMM
// ---------------------------------------------------------------------------
extern "C" void kernel_launch(void* const* d_in, const int* in_sizes, int n_in,
                              void* d_out, int out_size)
{
    const float* x  = (const float*)d_in[0];
    const unsigned int* mask = (const unsigned int*)d_in[1];  // bool promoted to 32-bit
    const float* wq = (const float*)d_in[2];
    const float* wk = (const float*)d_in[3];
    const float* wv = (const float*)d_in[4];
    const float* wo = (const float*)d_in[5];
    float* out = (float*)d_out;

    float *q, *k, *v, *attn;
    cudaGetSymbolAddress((void**)&q,    g_q);
    cudaGetSymbolAddress((void**)&k,    g_k);
    cudaGetSymbolAddress((void**)&v,    g_v);
    cudaGetSymbolAddress((void**)&attn, g_attn);

    dim3 gp(Dq / 128, Mq / 128);   // (8, 64)
    gemm_nt<<<gp, 256>>>(x, wq, q, Mq, Dq, Dq);
    gemm_nt<<<gp, 256>>>(x, wk, k, Mq, Dq, Dq);
    gemm_nt<<<gp, 256>>>(x, wv, v, Mq, Dq, Dq);

    const int smem_bytes = 4 * 64 * PADK * sizeof(float);  // 69632
    cudaFuncSetAttribute(attn_fused, cudaFuncAttributeMaxDynamicSharedMemorySize, smem_bytes);
    attn_fused<<<dim3(Sq / 64, Bq * Hq), 256, smem_bytes>>>(q, k, v, mask, attn);

    gemm_nt<<<gp, 256>>>(attn, wo, out, Mq, Dq, Dq);
}

// round 3
// speedup vs baseline: 2.4867x; 2.4867x over previous
#include <cuda_runtime.h>
#include <cuda_bf16.h>
#include <cstdint>
#include <cstddef>

// Problem constants
#define Bq  4
#define Sq  2048
#define Dq  1024
#define Hq  16
#define HDq 64
#define Mq  (Bq * Sq)   // 8192

// Scratch: Q, K, V, attn-out in [B, S, D] layout (head h occupies cols h*64..h*64+63)
__device__ float g_q[(size_t)Mq * Dq];
__device__ float g_k[(size_t)Mq * Dq];
__device__ float g_v[(size_t)Mq * Dq];
__device__ float g_attn[(size_t)Mq * Dq];

// ---------------------------------------------------------------------------
// Tensor-core NT GEMM with bf16x2 split (3-pass) for ~fp32 precision.
// C[M,N] = A[M,K] @ W[N,K]^T.
// Tile: BM=BN=128, BK=32, 256 threads (8 warps as 2x4), warp tile 64x32.
// Fragments via ldmatrix.x4 from bf16 smem (pitch 40 -> conflict-free).
// ---------------------------------------------------------------------------
#define GPITCH 40   // bf16 elements per smem row (80 bytes: 16B-aligned, 20-bank stride)

__device__ __forceinline__ void mma_bf16(float& d0, float& d1, float& d2, float& d3,
                                         uint32_t a0, uint32_t a1, uint32_t a2, uint32_t a3,
                                         uint32_t b0, uint32_t b1)
{
    asm volatile(
        "mma.sync.aligned.m16n8k16.row.col.f32.bf16.bf16.f32 "
        "{%0,%1,%2,%3}, {%4,%5,%6,%7}, {%8,%9}, {%0,%1,%2,%3};"
        : "+f"(d0), "+f"(d1), "+f"(d2), "+f"(d3)
        : "r"(a0), "r"(a1), "r"(a2), "r"(a3), "r"(b0), "r"(b1));
}

__device__ __forceinline__ void ldm_x4(uint32_t& r0, uint32_t& r1, uint32_t& r2, uint32_t& r3,
                                       uint32_t addr)
{
    asm volatile("ldmatrix.sync.aligned.m8n8.x4.shared.b16 {%0,%1,%2,%3}, [%4];"
                 : "=r"(r0), "=r"(r1), "=r"(r2), "=r"(r3) : "r"(addr));
}

__global__ __launch_bounds__(256) void gemm_nt_tc(
    const float* __restrict__ A, const float* __restrict__ W,
    float* __restrict__ C, int M, int N, int K)
{
    __shared__ __nv_bfloat16 Ah[128 * GPITCH];
    __shared__ __nv_bfloat16 Al[128 * GPITCH];
    __shared__ __nv_bfloat16 Wh[128 * GPITCH];
    __shared__ __nv_bfloat16 Wl[128 * GPITCH];

    const int tid  = threadIdx.x;
    const int wid  = tid >> 5;
    const int lane = tid & 31;
    const int wm = wid >> 2;          // 0..1 -> m offset 64*wm
    const int wn = wid & 3;           // 0..3 -> n offset 32*wn
    const int bm = blockIdx.y * 128;
    const int bn = blockIdx.x * 128;

    float c[4][4][4];                 // [m-tile][n-tile][reg]
    #pragma unroll
    for (int i = 0; i < 4; i++)
        #pragma unroll
        for (int j = 0; j < 4; j++)
            #pragma unroll
            for (int r = 0; r < 4; r++) c[i][j][r] = 0.f;

    const uint32_t ah_base = (uint32_t)__cvta_generic_to_shared(Ah);
    const uint32_t al_base = (uint32_t)__cvta_generic_to_shared(Al);
    const uint32_t wh_base = (uint32_t)__cvta_generic_to_shared(Wh);
    const uint32_t wl_base = (uint32_t)__cvta_generic_to_shared(Wl);

    // ldmatrix lane->row/koffset mapping (same for A tiles and W n-tile pairs):
    //   matrix idx m = lane>>3; row-in-group = lane&7
    const int lm  = lane >> 3;        // 0..3
    const int lr  = lane & 7;         // 0..7

    for (int k0 = 0; k0 < K; k0 += 32) {
        // -------- global load + bf16 hi/lo split --------
        #pragma unroll
        for (int i = 0; i < 4; i++) {
            int lin = tid + i * 256;
            int row = lin >> 3;           // 0..127
            int cc  = (lin & 7) * 4;      // 0..28
            float4 a = *(const float4*)(A + (size_t)(bm + row) * K + k0 + cc);
            float4 w = *(const float4*)(W + (size_t)(bn + row) * K + k0 + cc);
            int o = row * GPITCH + cc;
            float av[4] = {a.x, a.y, a.z, a.w};
            float wv[4] = {w.x, w.y, w.z, w.w};
            #pragma unroll
            for (int e = 0; e < 4; e++) {
                __nv_bfloat16 hi = __float2bfloat16(av[e]);
                Ah[o + e] = hi;
                Al[o + e] = __float2bfloat16(av[e] - __bfloat162float(hi));
                __nv_bfloat16 wh = __float2bfloat16(wv[e]);
                Wh[o + e] = wh;
                Wl[o + e] = __float2bfloat16(wv[e] - __bfloat162float(wh));
            }
        }
        __syncthreads();

        #pragma unroll
        for (int ks = 0; ks < 2; ks++) {           // two k16 steps per BK=32
            const int kbyteA = ks * 32 + ((lm >> 1) & 1) * 16;  // A: matrices 0,1 k0-7; 2,3 k8-15
            // A fragment addresses: matrices (rows0-7,k0-7),(rows8-15,k0-7),(rows0-7,k8),(rows8-15,k8)
            // lane groups 0-7/8-15/16-23/24-31 -> matrix 0..3
            const int a_row_in16 = lr + ((lm & 1) << 3);
            const int a_kbyte    = ks * 32 + ((lm >> 1) << 4);

            uint32_t a_hi[4][4], a_lo[4][4];
            #pragma unroll
            for (int mt = 0; mt < 4; mt++) {
                uint32_t off = (uint32_t)((wm * 64 + mt * 16 + a_row_in16) * GPITCH) * 2 + a_kbyte;
                ldm_x4(a_hi[mt][0], a_hi[mt][1], a_hi[mt][2], a_hi[mt][3], ah_base + off);
                ldm_x4(a_lo[mt][0], a_lo[mt][1], a_lo[mt][2], a_lo[mt][3], al_base + off);
            }

            // B fragments: two x4 loads cover n-tiles {0,1} and {2,3}.
            // matrices: (ntile even, k0-7),(ntile even, k8-15),(ntile odd, k0-7),(ntile odd, k8-15)
            uint32_t b_hi[4][2], b_lo[4][2];
            #pragma unroll
            for (int p = 0; p < 2; p++) {
                int ntile = p * 2 + (lm >> 1);
                int n_row = wn * 32 + ntile * 8 + lr;
                uint32_t off = (uint32_t)(n_row * GPITCH) * 2 + (uint32_t)(ks * 32 + ((lm & 1) << 4));
                uint32_t r0, r1, r2, r3;
                ldm_x4(r0, r1, r2, r3, wh_base + off);
                b_hi[p * 2 + 0][0] = r0; b_hi[p * 2 + 0][1] = r1;
                b_hi[p * 2 + 1][0] = r2; b_hi[p * 2 + 1][1] = r3;
                ldm_x4(r0, r1, r2, r3, wl_base + off);
                b_lo[p * 2 + 0][0] = r0; b_lo[p * 2 + 0][1] = r1;
                b_lo[p * 2 + 1][0] = r2; b_lo[p * 2 + 1][1] = r3;
            }
            (void)kbyteA;

            #pragma unroll
            for (int mt = 0; mt < 4; mt++)
                #pragma unroll
                for (int nt = 0; nt < 4; nt++) {
                    mma_bf16(c[mt][nt][0], c[mt][nt][1], c[mt][nt][2], c[mt][nt][3],
                             a_hi[mt][0], a_hi[mt][1], a_hi[mt][2], a_hi[mt][3],
                             b_hi[nt][0], b_hi[nt][1]);
                    mma_bf16(c[mt][nt][0], c[mt][nt][1], c[mt][nt][2], c[mt][nt][3],
                             a_hi[mt][0], a_hi[mt][1], a_hi[mt][2], a_hi[mt][3],
                             b_lo[nt][0], b_lo[nt][1]);
                    mma_bf16(c[mt][nt][0], c[mt][nt][1], c[mt][nt][2], c[mt][nt][3],
                             a_lo[mt][0], a_lo[mt][1], a_lo[mt][2], a_lo[mt][3],
                             b_hi[nt][0], b_hi[nt][1]);
                }
        }
        __syncthreads();
    }

    // -------- epilogue --------
    const int g  = lane >> 2;   // 0..7
    const int t2 = lane & 3;    // 0..3
    #pragma unroll
    for (int mt = 0; mt < 4; mt++) {
        #pragma unroll
        for (int nt = 0; nt < 4; nt++) {
            int row0 = bm + wm * 64 + mt * 16 + g;
            int col  = bn + wn * 32 + nt * 8 + t2 * 2;
            *(float2*)(C + (size_t)row0 * N + col)       = make_float2(c[mt][nt][0], c[mt][nt][1]);
            *(float2*)(C + (size_t)(row0 + 8) * N + col) = make_float2(c[mt][nt][2], c[mt][nt][3]);
        }
    }
}

// ---------------------------------------------------------------------------
// Flash-style attention (unchanged from R2). One block = 64 query rows of one
// (b,h). Mask read as 32-bit words; nonzero == keep.
// ---------------------------------------------------------------------------
#define PADK 68   // smem leading dim (floats)

__global__ __launch_bounds__(256) void attn_fused(
    const float* __restrict__ Q, const float* __restrict__ K,
    const float* __restrict__ V, const unsigned int* __restrict__ mask,
    float* __restrict__ O)
{
    extern __shared__ float sm[];
    float* Qs = sm;                  // [64][PADK]  row-major (q, hd)
    float* Kt = sm + 64 * PADK;      // [64][PADK]  transposed (hd, s)
    float* Vs = sm + 2 * 64 * PADK;  // [64][PADK]  row-major (s, hd)
    float* Ps = sm + 3 * 64 * PADK;  // [64][PADK]  row-major (q, s)

    const int tid = threadIdx.x;
    const int tx = tid & 15;
    const int ty = tid >> 4;
    const int bh = blockIdx.y;       // 0..63
    const int b  = bh >> 4;
    const int h  = bh & 15;
    const int q0 = blockIdx.x * 64;

    const float* Qg = Q + (size_t)b * Sq * Dq + (size_t)h * HDq;
    const float* Kg = K + (size_t)b * Sq * Dq + (size_t)h * HDq;
    const float* Vg = V + (size_t)b * Sq * Dq + (size_t)h * HDq;
    const unsigned int* Mg = mask + (size_t)b * Sq * Sq;

    #pragma unroll
    for (int i = 0; i < 4; i++) {
        int lin = tid + i * 256;
        int r = lin >> 4;
        int c = (lin & 15) << 2;
        *(float4*)&Qs[r * PADK + c] = *(const float4*)(Qg + (size_t)(q0 + r) * Dq + c);
    }

    float m_i[4], l_i[4], acc[4][4];
    #pragma unroll
    for (int i = 0; i < 4; i++) {
        m_i[i] = -1e30f; l_i[i] = 0.f;
        #pragma unroll
        for (int j = 0; j < 4; j++) acc[i][j] = 0.f;
    }

    for (int kb = 0; kb < Sq; kb += 64) {
        __syncthreads();

        #pragma unroll
        for (int i = 0; i < 4; i++) {
            int lin = tid + i * 256;
            int r = lin >> 4;
            int c = (lin & 15) << 2;
            float4 kv = *(const float4*)(Kg + (size_t)(kb + r) * Dq + c);
            Kt[(c + 0) * PADK + r] = kv.x;
            Kt[(c + 1) * PADK + r] = kv.y;
            Kt[(c + 2) * PADK + r] = kv.z;
            Kt[(c + 3) * PADK + r] = kv.w;
            *(float4*)&Vs[r * PADK + c] = *(const float4*)(Vg + (size_t)(kb + r) * Dq + c);
        }
        __syncthreads();

        float s[4][4];
        #pragma unroll
        for (int i = 0; i < 4; i++)
            #pragma unroll
            for (int j = 0; j < 4; j++) s[i][j] = 0.f;

        #pragma unroll 8
        for (int k = 0; k < 64; k++) {
            float4 bv = *(const float4*)&Kt[k * PADK + tx * 4];
            float a0 = Qs[(ty * 4 + 0) * PADK + k];
            float a1 = Qs[(ty * 4 + 1) * PADK + k];
            float a2 = Qs[(ty * 4 + 2) * PADK + k];
            float a3 = Qs[(ty * 4 + 3) * PADK + k];
            s[0][0] = fmaf(a0, bv.x, s[0][0]); s[0][1] = fmaf(a0, bv.y, s[0][1]);
            s[0][2] = fmaf(a0, bv.z, s[0][2]); s[0][3] = fmaf(a0, bv.w, s[0][3]);
            s[1][0] = fmaf(a1, bv.x, s[1][0]); s[1][1] = fmaf(a1, bv.y, s[1][1]);
            s[1][2] = fmaf(a1, bv.z, s[1][2]); s[1][3] = fmaf(a1, bv.w, s[1][3]);
            s[2][0] = fmaf(a2, bv.x, s[2][0]); s[2][1] = fmaf(a2, bv.y, s[2][1]);
            s[2][2] = fmaf(a2, bv.z, s[2][2]); s[2][3] = fmaf(a2, bv.w, s[2][3]);
            s[3][0] = fmaf(a3, bv.x, s[3][0]); s[3][1] = fmaf(a3, bv.y, s[3][1]);
            s[3][2] = fmaf(a3, bv.z, s[3][2]); s[3][3] = fmaf(a3, bv.w, s[3][3]);
        }

        #pragma unroll
        for (int i = 0; i < 4; i++) {
            const uint4 mv = *(const uint4*)(Mg + (size_t)(q0 + ty * 4 + i) * Sq + kb + tx * 4);
            const bool mk[4] = {mv.x != 0u, mv.y != 0u, mv.z != 0u, mv.w != 0u};
            float rmax = -1e30f;
            #pragma unroll
            for (int j = 0; j < 4; j++) {
                s[i][j] *= 0.125f;
                if (!mk[j]) s[i][j] = -1e30f;
                rmax = fmaxf(rmax, s[i][j]);
            }
            #pragma unroll
            for (int o = 8; o >= 1; o >>= 1)
                rmax = fmaxf(rmax, __shfl_xor_sync(0xffffffffu, rmax, o));

            float mnew = fmaxf(m_i[i], rmax);
            float p[4]; float rsum = 0.f;
            #pragma unroll
            for (int j = 0; j < 4; j++) {
                p[j] = mk[j] ? __expf(s[i][j] - mnew) : 0.f;
                rsum += p[j];
            }
            *(float4*)&Ps[(ty * 4 + i) * PADK + tx * 4] = make_float4(p[0], p[1], p[2], p[3]);
            #pragma unroll
            for (int o = 8; o >= 1; o >>= 1)
                rsum += __shfl_xor_sync(0xffffffffu, rsum, o);

            float alpha = __expf(m_i[i] - mnew);
            l_i[i] = l_i[i] * alpha + rsum;
            m_i[i] = mnew;
            #pragma unroll
            for (int j = 0; j < 4; j++) acc[i][j] *= alpha;
        }
        __syncthreads();

        #pragma unroll 8
        for (int k = 0; k < 64; k++) {
            float4 bv = *(const float4*)&Vs[k * PADK + tx * 4];
            float a0 = Ps[(ty * 4 + 0) * PADK + k];
            float a1 = Ps[(ty * 4 + 1) * PADK + k];
            float a2 = Ps[(ty * 4 + 2) * PADK + k];
            float a3 = Ps[(ty * 4 + 3) * PADK + k];
            acc[0][0] = fmaf(a0, bv.x, acc[0][0]); acc[0][1] = fmaf(a0, bv.y, acc[0][1]);
            acc[0][2] = fmaf(a0, bv.z, acc[0][2]); acc[0][3] = fmaf(a0, bv.w, acc[0][3]);
            acc[1][0] = fmaf(a1, bv.x, acc[1][0]); acc[1][1] = fmaf(a1, bv.y, acc[1][1]);
            acc[1][2] = fmaf(a1, bv.z, acc[1][2]); acc[1][3] = fmaf(a1, bv.w, acc[1][3]);
            acc[2][0] = fmaf(a2, bv.x, acc[2][0]); acc[2][1] = fmaf(a2, bv.y, acc[2][1]);
            acc[2][2] = fmaf(a2, bv.z, acc[2][2]); acc[2][3] = fmaf(a2, bv.w, acc[2][3]);
            acc[3][0] = fmaf(a3, bv.x, acc[3][0]); acc[3][1] = fmaf(a3, bv.y, acc[3][1]);
            acc[3][2] = fmaf(a3, bv.z, acc[3][2]); acc[3][3] = fmaf(a3, bv.w, acc[3][3]);
        }
    }

    float* Og = O + (size_t)b * Sq * Dq + (size_t)h * HDq;
    #pragma unroll
    for (int i = 0; i < 4; i++) {
        float inv = l_i[i] > 0.f ? 1.f / l_i[i] : 0.f;
        *(float4*)(Og + (size_t)(q0 + ty * 4 + i) * Dq + tx * 4) =
            make_float4(acc[i][0] * inv, acc[i][1] * inv, acc[i][2] * inv, acc[i][3] * inv);
    }
}

// ---------------------------------------------------------------------------
// Launch: 3 projection GEMMs (tensor core) -> fused attention -> output GEMM
// ---------------------------------------------------------------------------
extern "C" void kernel_launch(void* const* d_in, const int* in_sizes, int n_in,
                              void* d_out, int out_size)
{
    const float* x  = (const float*)d_in[0];
    const unsigned int* mask = (const unsigned int*)d_in[1];  // bool promoted to 32-bit
    const float* wq = (const float*)d_in[2];
    const float* wk = (const float*)d_in[3];
    const float* wv = (const float*)d_in[4];
    const float* wo = (const float*)d_in[5];
    float* out = (float*)d_out;

    float *q, *k, *v, *attn;
    cudaGetSymbolAddress((void**)&q,    g_q);
    cudaGetSymbolAddress((void**)&k,    g_k);
    cudaGetSymbolAddress((void**)&v,    g_v);
    cudaGetSymbolAddress((void**)&attn, g_attn);

    dim3 gp(Dq / 128, Mq / 128);   // (8, 64)
    gemm_nt_tc<<<gp, 256>>>(x, wq, q, Mq, Dq, Dq);
    gemm_nt_tc<<<gp, 256>>>(x, wk, k, Mq, Dq, Dq);
    gemm_nt_tc<<<gp, 256>>>(x, wv, v, Mq, Dq, Dq);

    const int smem_bytes = 4 * 64 * PADK * sizeof(float);  // 69632
    cudaFuncSetAttribute(attn_fused, cudaFuncAttributeMaxDynamicSharedMemorySize, smem_bytes);
    attn_fused<<<dim3(Sq / 64, Bq * Hq), 256, smem_bytes>>>(q, k, v, mask, attn);

    gemm_nt_tc<<<gp, 256>>>(attn, wo, out, Mq, Dq, Dq);
}

// round 5
// speedup vs baseline: 3.3633x; 1.3525x over previous
#include <cuda_runtime.h>
#include <cuda_bf16.h>
#include <cstdint>
#include <cstddef>

// Problem constants
#define Bq  4
#define Sq  2048
#define Dq  1024
#define Hq  16
#define HDq 64
#define Mq  (Bq * Sq)   // 8192

__device__ float g_q[(size_t)Mq * Dq];
__device__ float g_k[(size_t)Mq * Dq];
__device__ float g_v[(size_t)Mq * Dq];
__device__ float g_attn[(size_t)Mq * Dq];

// ---------------------------------------------------------------------------
// mma / ldmatrix helpers
// ---------------------------------------------------------------------------
__device__ __forceinline__ void mma_bf16(float& d0, float& d1, float& d2, float& d3,
                                         uint32_t a0, uint32_t a1, uint32_t a2, uint32_t a3,
                                         uint32_t b0, uint32_t b1)
{
    asm volatile(
        "mma.sync.aligned.m16n8k16.row.col.f32.bf16.bf16.f32 "
        "{%0,%1,%2,%3}, {%4,%5,%6,%7}, {%8,%9}, {%0,%1,%2,%3};"
        : "+f"(d0), "+f"(d1), "+f"(d2), "+f"(d3)
        : "r"(a0), "r"(a1), "r"(a2), "r"(a3), "r"(b0), "r"(b1));
}

__device__ __forceinline__ void ldm_x4(uint32_t& r0, uint32_t& r1, uint32_t& r2, uint32_t& r3,
                                       uint32_t addr)
{
    asm volatile("ldmatrix.sync.aligned.m8n8.x4.shared.b16 {%0,%1,%2,%3}, [%4];"
                 : "=r"(r0), "=r"(r1), "=r"(r2), "=r"(r3) : "r"(addr));
}

__device__ __forceinline__ uint32_t pack_bf16(float e0, float e1)   // e0 -> low half
{
    __nv_bfloat162 t = __floats2bfloat162_rn(e0, e1);
    return *(uint32_t*)&t;
}

// ---------------------------------------------------------------------------
// Tensor-core NT GEMM with bf16x2 split (3-pass). Unchanged from R3.
// ---------------------------------------------------------------------------
#define GPITCH 40

__global__ __launch_bounds__(256) void gemm_nt_tc(
    const float* __restrict__ A, const float* __restrict__ W,
    float* __restrict__ C, int M, int N, int K)
{
    __shared__ __nv_bfloat16 Ah[128 * GPITCH];
    __shared__ __nv_bfloat16 Al[128 * GPITCH];
    __shared__ __nv_bfloat16 Wh[128 * GPITCH];
    __shared__ __nv_bfloat16 Wl[128 * GPITCH];

    const int tid  = threadIdx.x;
    const int wid  = tid >> 5;
    const int lane = tid & 31;
    const int wm = wid >> 2;
    const int wn = wid & 3;
    const int bm = blockIdx.y * 128;
    const int bn = blockIdx.x * 128;

    float c[4][4][4];
    #pragma unroll
    for (int i = 0; i < 4; i++)
        #pragma unroll
        for (int j = 0; j < 4; j++)
            #pragma unroll
            for (int r = 0; r < 4; r++) c[i][j][r] = 0.f;

    const uint32_t ah_base = (uint32_t)__cvta_generic_to_shared(Ah);
    const uint32_t al_base = (uint32_t)__cvta_generic_to_shared(Al);
    const uint32_t wh_base = (uint32_t)__cvta_generic_to_shared(Wh);
    const uint32_t wl_base = (uint32_t)__cvta_generic_to_shared(Wl);

    const int lm  = lane >> 3;
    const int lr  = lane & 7;

    for (int k0 = 0; k0 < K; k0 += 32) {
        #pragma unroll
        for (int i = 0; i < 4; i++) {
            int lin = tid + i * 256;
            int row = lin >> 3;
            int cc  = (lin & 7) * 4;
            float4 a = *(const float4*)(A + (size_t)(bm + row) * K + k0 + cc);
            float4 w = *(const float4*)(W + (size_t)(bn + row) * K + k0 + cc);
            int o = row * GPITCH + cc;
            float av[4] = {a.x, a.y, a.z, a.w};
            float wv[4] = {w.x, w.y, w.z, w.w};
            #pragma unroll
            for (int e = 0; e < 4; e++) {
                __nv_bfloat16 hi = __float2bfloat16(av[e]);
                Ah[o + e] = hi;
                Al[o + e] = __float2bfloat16(av[e] - __bfloat162float(hi));
                __nv_bfloat16 wh = __float2bfloat16(wv[e]);
                Wh[o + e] = wh;
                Wl[o + e] = __float2bfloat16(wv[e] - __bfloat162float(wh));
            }
        }
        __syncthreads();

        #pragma unroll
        for (int ks = 0; ks < 2; ks++) {
            const int a_row_in16 = lr + ((lm & 1) << 3);
            const int a_kbyte    = ks * 32 + ((lm >> 1) << 4);

            uint32_t a_hi[4][4], a_lo[4][4];
            #pragma unroll
            for (int mt = 0; mt < 4; mt++) {
                uint32_t off = (uint32_t)((wm * 64 + mt * 16 + a_row_in16) * GPITCH) * 2 + a_kbyte;
                ldm_x4(a_hi[mt][0], a_hi[mt][1], a_hi[mt][2], a_hi[mt][3], ah_base + off);
                ldm_x4(a_lo[mt][0], a_lo[mt][1], a_lo[mt][2], a_lo[mt][3], al_base + off);
            }

            uint32_t b_hi[4][2], b_lo[4][2];
            #pragma unroll
            for (int p = 0; p < 2; p++) {
                int ntile = p * 2 + (lm >> 1);
                int n_row = wn * 32 + ntile * 8 + lr;
                uint32_t off = (uint32_t)(n_row * GPITCH) * 2 + (uint32_t)(ks * 32 + ((lm & 1) << 4));
                uint32_t r0, r1, r2, r3;
                ldm_x4(r0, r1, r2, r3, wh_base + off);
                b_hi[p * 2 + 0][0] = r0; b_hi[p * 2 + 0][1] = r1;
                b_hi[p * 2 + 1][0] = r2; b_hi[p * 2 + 1][1] = r3;
                ldm_x4(r0, r1, r2, r3, wl_base + off);
                b_lo[p * 2 + 0][0] = r0; b_lo[p * 2 + 0][1] = r1;
                b_lo[p * 2 + 1][0] = r2; b_lo[p * 2 + 1][1] = r3;
            }

            #pragma unroll
            for (int mt = 0; mt < 4; mt++)
                #pragma unroll
                for (int nt = 0; nt < 4; nt++) {
                    mma_bf16(c[mt][nt][0], c[mt][nt][1], c[mt][nt][2], c[mt][nt][3],
                             a_hi[mt][0], a_hi[mt][1], a_hi[mt][2], a_hi[mt][3],
                             b_hi[nt][0], b_hi[nt][1]);
                    mma_bf16(c[mt][nt][0], c[mt][nt][1], c[mt][nt][2], c[mt][nt][3],
                             a_hi[mt][0], a_hi[mt][1], a_hi[mt][2], a_hi[mt][3],
                             b_lo[nt][0], b_lo[nt][1]);
                    mma_bf16(c[mt][nt][0], c[mt][nt][1], c[mt][nt][2], c[mt][nt][3],
                             a_lo[mt][0], a_lo[mt][1], a_lo[mt][2], a_lo[mt][3],
                             b_hi[nt][0], b_hi[nt][1]);
                }
        }
        __syncthreads();
    }

    const int g  = lane >> 2;
    const int t2 = lane & 3;
    #pragma unroll
    for (int mt = 0; mt < 4; mt++) {
        #pragma unroll
        for (int nt = 0; nt < 4; nt++) {
            int row0 = bm + wm * 64 + mt * 16 + g;
            int col  = bn + wn * 32 + nt * 8 + t2 * 2;
            *(float2*)(C + (size_t)row0 * N + col)       = make_float2(c[mt][nt][0], c[mt][nt][1]);
            *(float2*)(C + (size_t)(row0 + 8) * N + col) = make_float2(c[mt][nt][2], c[mt][nt][3]);
        }
    }
}

// ---------------------------------------------------------------------------
// Tensor-core flash attention.
// Block = 128 q-rows of one (b,h); 8 warps; warp = 16 q-rows x all 64 keys.
// S = Q@K^T and O += P@V via mma.sync bf16 hi/lo 3-pass.
// Warp-local online softmax (quad shuffles). Mask packed to bits in smem.
// smem: Qh/Ql[128][72], Kh/Kl[64][72], Vth/Vtl[64][72] (V transposed), mb[128][2]
// ---------------------------------------------------------------------------
#define APITCH 72   // bf16 pitch (144 B) -> conflict-free ldmatrix

#define OFF_QH  0
#define OFF_QL  (OFF_QH + 128 * APITCH * 2)
#define OFF_KH  (OFF_QL + 128 * APITCH * 2)
#define OFF_KL  (OFF_KH + 64 * APITCH * 2)
#define OFF_VTH (OFF_KL + 64 * APITCH * 2)
#define OFF_VTL (OFF_VTH + 64 * APITCH * 2)
#define OFF_MB  (OFF_VTL + 64 * APITCH * 2)
#define ATTN_SMEM (OFF_MB + 128 * 2 * 4)

__global__ __launch_bounds__(256) void attn_tc(
    const float* __restrict__ Q, const float* __restrict__ K,
    const float* __restrict__ V, const unsigned int* __restrict__ mask,
    float* __restrict__ O)
{
    extern __shared__ char smem[];
    __nv_bfloat16* Qh  = (__nv_bfloat16*)(smem + OFF_QH);
    __nv_bfloat16* Ql  = (__nv_bfloat16*)(smem + OFF_QL);
    __nv_bfloat16* Kh  = (__nv_bfloat16*)(smem + OFF_KH);
    __nv_bfloat16* Kl  = (__nv_bfloat16*)(smem + OFF_KL);
    __nv_bfloat16* Vth = (__nv_bfloat16*)(smem + OFF_VTH);
    __nv_bfloat16* Vtl = (__nv_bfloat16*)(smem + OFF_VTL);
    unsigned int*  mb  = (unsigned int*)(smem + OFF_MB);

    const uint32_t qh_b  = (uint32_t)__cvta_generic_to_shared(Qh);
    const uint32_t ql_b  = (uint32_t)__cvta_generic_to_shared(Ql);
    const uint32_t kh_b  = (uint32_t)__cvta_generic_to_shared(Kh);
    const uint32_t kl_b  = (uint32_t)__cvta_generic_to_shared(Kl);
    const uint32_t vth_b = (uint32_t)__cvta_generic_to_shared(Vth);
    const uint32_t vtl_b = (uint32_t)__cvta_generic_to_shared(Vtl);

    const int tid  = threadIdx.x;
    const int wid  = tid >> 5;
    const int lane = tid & 31;
    const int lm   = lane >> 3;      // 0..3
    const int lr   = lane & 7;       // 0..7
    const int g    = lane >> 2;      // 0..7
    const int t2   = lane & 3;       // 0..3

    const int bh = blockIdx.y;
    const int b  = bh >> 4;
    const int h  = bh & 15;
    const int q0 = blockIdx.x * 128;

    const float* Qg = Q + (size_t)b * Sq * Dq + (size_t)h * HDq;
    const float* Kg = K + (size_t)b * Sq * Dq + (size_t)h * HDq;
    const float* Vg = V + (size_t)b * Sq * Dq + (size_t)h * HDq;
    const unsigned int* Mg = mask + (size_t)b * Sq * Sq;

    // ---- load Q tile (128 x 64), split hi/lo ----
    #pragma unroll
    for (int i = 0; i < 8; i++) {
        int lin = tid + i * 256;
        int r = lin >> 4;               // 0..127
        int c = (lin & 15) << 2;        // 0..60
        float4 qv = *(const float4*)(Qg + (size_t)(q0 + r) * Dq + c);
        float av[4] = {qv.x, qv.y, qv.z, qv.w};
        int o = r * APITCH + c;
        #pragma unroll
        for (int e = 0; e < 4; e++) {
            __nv_bfloat16 hi = __float2bfloat16(av[e]);
            Qh[o + e] = hi;
            Ql[o + e] = __float2bfloat16(av[e] - __bfloat162float(hi));
        }
    }
    __syncthreads();

    // ---- load Q fragments once (A operand, m16k16 x 4 ksteps) ----
    uint32_t qa_h[4][4], qa_l[4][4];
    {
        const int a_row = wid * 16 + lr + ((lm & 1) << 3);
        #pragma unroll
        for (int ks = 0; ks < 4; ks++) {
            uint32_t off = (uint32_t)(a_row * APITCH) * 2 + (uint32_t)(ks * 32 + ((lm >> 1) << 4));
            ldm_x4(qa_h[ks][0], qa_h[ks][1], qa_h[ks][2], qa_h[ks][3], qh_b + off);
            ldm_x4(qa_l[ks][0], qa_l[ks][1], qa_l[ks][2], qa_l[ks][3], ql_b + off);
        }
    }

    float o_acc[8][4];
    #pragma unroll
    for (int j = 0; j < 8; j++)
        #pragma unroll
        for (int r = 0; r < 4; r++) o_acc[j][r] = 0.f;
    float m0 = -1e30f, m1 = -1e30f, l0 = 0.f, l1 = 0.f;

    for (int kb = 0; kb < Sq; kb += 64) {
        __syncthreads();   // previous iteration's compute done

        // ---- load K (rows [key][hd]) and V transposed ([hd][key]), hi/lo ----
        #pragma unroll
        for (int i = 0; i < 4; i++) {
            int lin = tid + i * 256;
            int r = lin >> 4;            // key row 0..63
            int c = (lin & 15) << 2;     // hd col
            float4 kv = *(const float4*)(Kg + (size_t)(kb + r) * Dq + c);
            float av[4] = {kv.x, kv.y, kv.z, kv.w};
            int o = r * APITCH + c;
            #pragma unroll
            for (int e = 0; e < 4; e++) {
                __nv_bfloat16 hi = __float2bfloat16(av[e]);
                Kh[o + e] = hi;
                Kl[o + e] = __float2bfloat16(av[e] - __bfloat162float(hi));
            }
            float4 vv = *(const float4*)(Vg + (size_t)(kb + r) * Dq + c);
            float bv[4] = {vv.x, vv.y, vv.z, vv.w};
            #pragma unroll
            for (int e = 0; e < 4; e++) {
                __nv_bfloat16 hi = __float2bfloat16(bv[e]);
                Vth[(c + e) * APITCH + r] = hi;
                Vtl[(c + e) * APITCH + r] = __float2bfloat16(bv[e] - __bfloat162float(hi));
            }
        }
        // ---- pack mask bits: mb[row][half], bit i = keep(kb+half*32+i) ----
        {
            int row  = tid >> 1;
            int half = tid & 1;
            const uint4* mp = (const uint4*)(Mg + (size_t)(q0 + row) * Sq + kb + half * 32);
            unsigned int bits = 0;
            #pragma unroll
            for (int i = 0; i < 8; i++) {
                uint4 mv = mp[i];
                bits |= (unsigned)(mv.x != 0u) << (4 * i + 0);
                bits |= (unsigned)(mv.y != 0u) << (4 * i + 1);
                bits |= (unsigned)(mv.z != 0u) << (4 * i + 2);
                bits |= (unsigned)(mv.w != 0u) << (4 * i + 3);
            }
            mb[row * 2 + half] = bits;
        }
        __syncthreads();

        // ---- S = Q @ K^T  (3-pass bf16) ----
        float s[8][4];
        #pragma unroll
        for (int j = 0; j < 8; j++)
            #pragma unroll
            for (int r = 0; r < 4; r++) s[j][r] = 0.f;

        #pragma unroll
        for (int ks = 0; ks < 4; ks++) {
            #pragma unroll
            for (int p2 = 0; p2 < 4; p2++) {
                int ntile = p2 * 2 + (lm >> 1);
                uint32_t off = (uint32_t)((ntile * 8 + lr) * APITCH) * 2
                             + (uint32_t)(ks * 32 + ((lm & 1) << 4));
                uint32_t bh0, bh1, bh2, bh3, bl0, bl1, bl2, bl3;
                ldm_x4(bh0, bh1, bh2, bh3, kh_b + off);
                ldm_x4(bl0, bl1, bl2, bl3, kl_b + off);
                int n0 = p2 * 2, n1 = p2 * 2 + 1;
                mma_bf16(s[n0][0], s[n0][1], s[n0][2], s[n0][3],
                         qa_h[ks][0], qa_h[ks][1], qa_h[ks][2], qa_h[ks][3], bh0, bh1);
                mma_bf16(s[n1][0], s[n1][1], s[n1][2], s[n1][3],
                         qa_h[ks][0], qa_h[ks][1], qa_h[ks][2], qa_h[ks][3], bh2, bh3);
                mma_bf16(s[n0][0], s[n0][1], s[n0][2], s[n0][3],
                         qa_h[ks][0], qa_h[ks][1], qa_h[ks][2], qa_h[ks][3], bl0, bl1);
                mma_bf16(s[n1][0], s[n1][1], s[n1][2], s[n1][3],
                         qa_h[ks][0], qa_h[ks][1], qa_h[ks][2], qa_h[ks][3], bl2, bl3);
                mma_bf16(s[n0][0], s[n0][1], s[n0][2], s[n0][3],
                         qa_l[ks][0], qa_l[ks][1], qa_l[ks][2], qa_l[ks][3], bh0, bh1);
                mma_bf16(s[n1][0], s[n1][1], s[n1][2], s[n1][3],
                         qa_l[ks][0], qa_l[ks][1], qa_l[ks][2], qa_l[ks][3], bh2, bh3);
            }
        }

        // ---- masked online softmax (warp-local; rows g and g+8 of warp tile) ----
        const int r0 = wid * 16 + g;
        const int r1 = r0 + 8;
        {
            unsigned int w0 = mb[r0 * 2], w1 = mb[r0 * 2 + 1];
            unsigned int x0 = mb[r1 * 2], x1 = mb[r1 * 2 + 1];
            float rmax0 = -1e30f, rmax1 = -1e30f;
            #pragma unroll
            for (int j = 0; j < 8; j++) {
                unsigned int wr0 = (j < 4) ? w0 : w1;
                unsigned int wr1 = (j < 4) ? x0 : x1;
                int sh = ((j & 3) * 8) + t2 * 2;
                bool k00 = (wr0 >> sh) & 1, k01 = (wr0 >> (sh + 1)) & 1;
                bool k10 = (wr1 >> sh) & 1, k11 = (wr1 >> (sh + 1)) & 1;
                s[j][0] = k00 ? s[j][0] * 0.125f : -1e30f;
                s[j][1] = k01 ? s[j][1] * 0.125f : -1e30f;
                s[j][2] = k10 ? s[j][2] * 0.125f : -1e30f;
                s[j][3] = k11 ? s[j][3] * 0.125f : -1e30f;
                rmax0 = fmaxf(rmax0, fmaxf(s[j][0], s[j][1]));
                rmax1 = fmaxf(rmax1, fmaxf(s[j][2], s[j][3]));
            }
            rmax0 = fmaxf(rmax0, __shfl_xor_sync(0xffffffffu, rmax0, 1));
            rmax0 = fmaxf(rmax0, __shfl_xor_sync(0xffffffffu, rmax0, 2));
            rmax1 = fmaxf(rmax1, __shfl_xor_sync(0xffffffffu, rmax1, 1));
            rmax1 = fmaxf(rmax1, __shfl_xor_sync(0xffffffffu, rmax1, 2));

            float mn0 = fmaxf(m0, rmax0);
            float mn1 = fmaxf(m1, rmax1);
            float rs0 = 0.f, rs1 = 0.f;
            #pragma unroll
            for (int j = 0; j < 8; j++) {
                s[j][0] = (s[j][0] > -1e29f) ? __expf(s[j][0] - mn0) : 0.f;
                s[j][1] = (s[j][1] > -1e29f) ? __expf(s[j][1] - mn0) : 0.f;
                s[j][2] = (s[j][2] > -1e29f) ? __expf(s[j][2] - mn1) : 0.f;
                s[j][3] = (s[j][3] > -1e29f) ? __expf(s[j][3] - mn1) : 0.f;
                rs0 += s[j][0] + s[j][1];
                rs1 += s[j][2] + s[j][3];
            }
            rs0 += __shfl_xor_sync(0xffffffffu, rs0, 1);
            rs0 += __shfl_xor_sync(0xffffffffu, rs0, 2);
            rs1 += __shfl_xor_sync(0xffffffffu, rs1, 1);
            rs1 += __shfl_xor_sync(0xffffffffu, rs1, 2);

            float al0 = __expf(m0 - mn0);
            float al1 = __expf(m1 - mn1);
            l0 = l0 * al0 + rs0; m0 = mn0;
            l1 = l1 * al1 + rs1; m1 = mn1;
            #pragma unroll
            for (int j = 0; j < 8; j++) {
                o_acc[j][0] *= al0; o_acc[j][1] *= al0;
                o_acc[j][2] *= al1; o_acc[j][3] *= al1;
            }
        }

        // ---- O += P @ V  (P from s regs, hi/lo; V from Vt smem, hi/lo) ----
        #pragma unroll
        for (int kk = 0; kk < 4; kk++) {
            int ja = 2 * kk, jb = 2 * kk + 1;
            uint32_t pah[4], pal[4];
            {
                uint32_t h0 = pack_bf16(s[ja][0], s[ja][1]);
                uint32_t h1 = pack_bf16(s[ja][2], s[ja][3]);
                uint32_t h2 = pack_bf16(s[jb][0], s[jb][1]);
                uint32_t h3 = pack_bf16(s[jb][2], s[jb][3]);
                pah[0] = h0; pah[1] = h1; pah[2] = h2; pah[3] = h3;
                __nv_bfloat162 t;
                t = *(__nv_bfloat162*)&h0;
                pal[0] = pack_bf16(s[ja][0] - __bfloat162float(t.x), s[ja][1] - __bfloat162float(t.y));
                t = *(__nv_bfloat162*)&h1;
                pal[1] = pack_bf16(s[ja][2] - __bfloat162float(t.x), s[ja][3] - __bfloat162float(t.y));
                t = *(__nv_bfloat162*)&h2;
                pal[2] = pack_bf16(s[jb][0] - __bfloat162float(t.x), s[jb][1] - __bfloat162float(t.y));
                t = *(__nv_bfloat162*)&h3;
                pal[3] = pack_bf16(s[jb][2] - __bfloat162float(t.x), s[jb][3] - __bfloat162float(t.y));
            }
            #pragma unroll
            for (int p2 = 0; p2 < 4; p2++) {
                int ntile = p2 * 2 + (lm >> 1);
                uint32_t off = (uint32_t)((ntile * 8 + lr) * APITCH) * 2
                             + (uint32_t)(kk * 32 + ((lm & 1) << 4));
                uint32_t bh0, bh1, bh2, bh3, bl0, bl1, bl2, bl3;
                ldm_x4(bh0, bh1, bh2, bh3, vth_b + off);
                ldm_x4(bl0, bl1, bl2, bl3, vtl_b + off);
                int n0 = p2 * 2, n1 = p2 * 2 + 1;
                mma_bf16(o_acc[n0][0], o_acc[n0][1], o_acc[n0][2], o_acc[n0][3],
                         pah[0], pah[1], pah[2], pah[3], bh0, bh1);
                mma_bf16(o_acc[n1][0], o_acc[n1][1], o_acc[n1][2], o_acc[n1][3],
                         pah[0], pah[1], pah[2], pah[3], bh2, bh3);
                mma_bf16(o_acc[n0][0], o_acc[n0][1], o_acc[n0][2], o_acc[n0][3],
                         pah[0], pah[1], pah[2], pah[3], bl0, bl1);
                mma_bf16(o_acc[n1][0], o_acc[n1][1], o_acc[n1][2], o_acc[n1][3],
                         pah[0], pah[1], pah[2], pah[3], bl2, bl3);
                mma_bf16(o_acc[n0][0], o_acc[n0][1], o_acc[n0][2], o_acc[n0][3],
                         pal[0], pal[1], pal[2], pal[3], bh0, bh1);
                mma_bf16(o_acc[n1][0], o_acc[n1][1], o_acc[n1][2], o_acc[n1][3],
                         pal[0], pal[1], pal[2], pal[3], bh2, bh3);
            }
        }
    }

    // ---- epilogue: normalize, store ----
    const float inv0 = l0 > 0.f ? 1.f / l0 : 0.f;
    const float inv1 = l1 > 0.f ? 1.f / l1 : 0.f;
    float* Og = O + (size_t)b * Sq * Dq + (size_t)h * HDq;
    const int row0 = q0 + wid * 16 + g;
    #pragma unroll
    for (int j = 0; j < 8; j++) {
        int col = j * 8 + t2 * 2;
        *(float2*)(Og + (size_t)row0 * Dq + col) =
            make_float2(o_acc[j][0] * inv0, o_acc[j][1] * inv0);
        *(float2*)(Og + (size_t)(row0 + 8) * Dq + col) =
            make_float2(o_acc[j][2] * inv1, o_acc[j][3] * inv1);
    }
}

// ---------------------------------------------------------------------------
// Launch
// ---------------------------------------------------------------------------
extern "C" void kernel_launch(void* const* d_in, const int* in_sizes, int n_in,
                              void* d_out, int out_size)
{
    const float* x  = (const float*)d_in[0];
    const unsigned int* mask = (const unsigned int*)d_in[1];
    const float* wq = (const float*)d_in[2];
    const float* wk = (const float*)d_in[3];
    const float* wv = (const float*)d_in[4];
    const float* wo = (const float*)d_in[5];
    float* out = (float*)d_out;

    float *q, *k, *v, *attn;
    cudaGetSymbolAddress((void**)&q,    g_q);
    cudaGetSymbolAddress((void**)&k,    g_k);
    cudaGetSymbolAddress((void**)&v,    g_v);
    cudaGetSymbolAddress((void**)&attn, g_attn);

    dim3 gp(Dq / 128, Mq / 128);
    gemm_nt_tc<<<gp, 256>>>(x, wq, q, Mq, Dq, Dq);
    gemm_nt_tc<<<gp, 256>>>(x, wk, k, Mq, Dq, Dq);
    gemm_nt_tc<<<gp, 256>>>(x, wv, v, Mq, Dq, Dq);

    cudaFuncSetAttribute(attn_tc, cudaFuncAttributeMaxDynamicSharedMemorySize, ATTN_SMEM);
    attn_tc<<<dim3(Sq / 128, Bq * Hq), 256, ATTN_SMEM>>>(q, k, v, mask, attn);

    gemm_nt_tc<<<gp, 256>>>(attn, wo, out, Mq, Dq, Dq);
}

// round 7
// speedup vs baseline: 4.1139x; 1.2232x over previous
#include <cuda_runtime.h>
#include <cuda_bf16.h>
#include <cstdint>
#include <cstddef>

// Problem constants
#define Bq  4
#define Sq  2048
#define Dq  1024
#define Hq  16
#define HDq 64
#define Mq  (Bq * Sq)   // 8192

// Scratch
__device__ __nv_bfloat16 g_qh[(size_t)Mq * Dq];
__device__ __nv_bfloat16 g_ql[(size_t)Mq * Dq];
__device__ __nv_bfloat16 g_kh[(size_t)Mq * Dq];
__device__ __nv_bfloat16 g_kl[(size_t)Mq * Dq];
__device__ __nv_bfloat16 g_vh[(size_t)Mq * Dq];
__device__ __nv_bfloat16 g_vl[(size_t)Mq * Dq];
__device__ __nv_bfloat16 g_vth[(size_t)Mq * Dq];   // [B,H,HD,S]
__device__ __nv_bfloat16 g_vtl[(size_t)Mq * Dq];   // [B,H,HD,S]
__device__ unsigned int  g_mbits[(size_t)Bq * Sq * (Sq / 32)];
__device__ float         g_attn[(size_t)Mq * Dq];

// ---------------------------------------------------------------------------
// helpers
// ---------------------------------------------------------------------------
__device__ __forceinline__ void mma_bf16(float& d0, float& d1, float& d2, float& d3,
                                         uint32_t a0, uint32_t a1, uint32_t a2, uint32_t a3,
                                         uint32_t b0, uint32_t b1)
{
    asm volatile(
        "mma.sync.aligned.m16n8k16.row.col.f32.bf16.bf16.f32 "
        "{%0,%1,%2,%3}, {%4,%5,%6,%7}, {%8,%9}, {%0,%1,%2,%3};"
        : "+f"(d0), "+f"(d1), "+f"(d2), "+f"(d3)
        : "r"(a0), "r"(a1), "r"(a2), "r"(a3), "r"(b0), "r"(b1));
}

__device__ __forceinline__ void ldm_x4(uint32_t& r0, uint32_t& r1, uint32_t& r2, uint32_t& r3,
                                       uint32_t addr)
{
    asm volatile("ldmatrix.sync.aligned.m8n8.x4.shared.b16 {%0,%1,%2,%3}, [%4];"
                 : "=r"(r0), "=r"(r1), "=r"(r2), "=r"(r3) : "r"(addr));
}

__device__ __forceinline__ uint32_t pack_bf16(float e0, float e1)
{
    __nv_bfloat162 t = __floats2bfloat162_rn(e0, e1);
    return *(uint32_t*)&t;
}

__device__ __forceinline__ void cpa16(uint32_t saddr, const void* gptr)
{
    asm volatile("cp.async.cg.shared.global [%0], [%1], 16;" :: "r"(saddr), "l"(gptr));
}
__device__ __forceinline__ void cpa_commit() { asm volatile("cp.async.commit_group;"); }
template<int N> __device__ __forceinline__ void cpa_wait()
{ asm volatile("cp.async.wait_group %0;" :: "n"(N) : "memory"); }

// ---------------------------------------------------------------------------
// Tensor-core NT GEMM, bf16x2 3-pass. BF16OUT: write hi/lo bf16 arrays.
// ---------------------------------------------------------------------------
#define GPITCH 40

template<bool BF16OUT>
__global__ __launch_bounds__(256) void gemm_nt_tc(
    const float* __restrict__ A, const float* __restrict__ W,
    float* __restrict__ C, __nv_bfloat16* __restrict__ Ch, __nv_bfloat16* __restrict__ Cl,
    int M, int N, int K)
{
    __shared__ __nv_bfloat16 Ah[128 * GPITCH];
    __shared__ __nv_bfloat16 Al[128 * GPITCH];
    __shared__ __nv_bfloat16 Wh[128 * GPITCH];
    __shared__ __nv_bfloat16 Wl[128 * GPITCH];

    const int tid  = threadIdx.x;
    const int wid  = tid >> 5;
    const int lane = tid & 31;
    const int wm = wid >> 2;
    const int wn = wid & 3;
    const int bm = blockIdx.y * 128;
    const int bn = blockIdx.x * 128;

    float c[4][4][4];
    #pragma unroll
    for (int i = 0; i < 4; i++)
        #pragma unroll
        for (int j = 0; j < 4; j++)
            #pragma unroll
            for (int r = 0; r < 4; r++) c[i][j][r] = 0.f;

    const uint32_t ah_base = (uint32_t)__cvta_generic_to_shared(Ah);
    const uint32_t al_base = (uint32_t)__cvta_generic_to_shared(Al);
    const uint32_t wh_base = (uint32_t)__cvta_generic_to_shared(Wh);
    const uint32_t wl_base = (uint32_t)__cvta_generic_to_shared(Wl);

    const int lm  = lane >> 3;
    const int lr  = lane & 7;

    for (int k0 = 0; k0 < K; k0 += 32) {
        #pragma unroll
        for (int i = 0; i < 4; i++) {
            int lin = tid + i * 256;
            int row = lin >> 3;
            int cc  = (lin & 7) * 4;
            float4 a = *(const float4*)(A + (size_t)(bm + row) * K + k0 + cc);
            float4 w = *(const float4*)(W + (size_t)(bn + row) * K + k0 + cc);
            int o = row * GPITCH + cc;
            float av[4] = {a.x, a.y, a.z, a.w};
            float wv[4] = {w.x, w.y, w.z, w.w};
            #pragma unroll
            for (int e = 0; e < 4; e++) {
                __nv_bfloat16 hi = __float2bfloat16(av[e]);
                Ah[o + e] = hi;
                Al[o + e] = __float2bfloat16(av[e] - __bfloat162float(hi));
                __nv_bfloat16 wh = __float2bfloat16(wv[e]);
                Wh[o + e] = wh;
                Wl[o + e] = __float2bfloat16(wv[e] - __bfloat162float(wh));
            }
        }
        __syncthreads();

        #pragma unroll
        for (int ks = 0; ks < 2; ks++) {
            const int a_row_in16 = lr + ((lm & 1) << 3);
            const int a_kbyte    = ks * 32 + ((lm >> 1) << 4);

            uint32_t a_hi[4][4], a_lo[4][4];
            #pragma unroll
            for (int mt = 0; mt < 4; mt++) {
                uint32_t off = (uint32_t)((wm * 64 + mt * 16 + a_row_in16) * GPITCH) * 2 + a_kbyte;
                ldm_x4(a_hi[mt][0], a_hi[mt][1], a_hi[mt][2], a_hi[mt][3], ah_base + off);
                ldm_x4(a_lo[mt][0], a_lo[mt][1], a_lo[mt][2], a_lo[mt][3], al_base + off);
            }

            uint32_t b_hi[4][2], b_lo[4][2];
            #pragma unroll
            for (int p = 0; p < 2; p++) {
                int ntile = p * 2 + (lm >> 1);
                int n_row = wn * 32 + ntile * 8 + lr;
                uint32_t off = (uint32_t)(n_row * GPITCH) * 2 + (uint32_t)(ks * 32 + ((lm & 1) << 4));
                uint32_t r0, r1, r2, r3;
                ldm_x4(r0, r1, r2, r3, wh_base + off);
                b_hi[p * 2 + 0][0] = r0; b_hi[p * 2 + 0][1] = r1;
                b_hi[p * 2 + 1][0] = r2; b_hi[p * 2 + 1][1] = r3;
                ldm_x4(r0, r1, r2, r3, wl_base + off);
                b_lo[p * 2 + 0][0] = r0; b_lo[p * 2 + 0][1] = r1;
                b_lo[p * 2 + 1][0] = r2; b_lo[p * 2 + 1][1] = r3;
            }

            #pragma unroll
            for (int mt = 0; mt < 4; mt++)
                #pragma unroll
                for (int nt = 0; nt < 4; nt++) {
                    mma_bf16(c[mt][nt][0], c[mt][nt][1], c[mt][nt][2], c[mt][nt][3],
                             a_hi[mt][0], a_hi[mt][1], a_hi[mt][2], a_hi[mt][3],
                             b_hi[nt][0], b_hi[nt][1]);
                    mma_bf16(c[mt][nt][0], c[mt][nt][1], c[mt][nt][2], c[mt][nt][3],
                             a_hi[mt][0], a_hi[mt][1], a_hi[mt][2], a_hi[mt][3],
                             b_lo[nt][0], b_lo[nt][1]);
                    mma_bf16(c[mt][nt][0], c[mt][nt][1], c[mt][nt][2], c[mt][nt][3],
                             a_lo[mt][0], a_lo[mt][1], a_lo[mt][2], a_lo[mt][3],
                             b_hi[nt][0], b_hi[nt][1]);
                }
        }
        __syncthreads();
    }

    const int g  = lane >> 2;
    const int t2 = lane & 3;
    #pragma unroll
    for (int mt = 0; mt < 4; mt++) {
        #pragma unroll
        for (int nt = 0; nt < 4; nt++) {
            int row0 = bm + wm * 64 + mt * 16 + g;
            int col  = bn + wn * 32 + nt * 8 + t2 * 2;
            if (BF16OUT) {
                #pragma unroll
                for (int half = 0; half < 2; half++) {
                    float v0 = c[mt][nt][half * 2], v1 = c[mt][nt][half * 2 + 1];
                    __nv_bfloat162 hi = __floats2bfloat162_rn(v0, v1);
                    __nv_bfloat162 lo = __floats2bfloat162_rn(v0 - __bfloat162float(hi.x),
                                                              v1 - __bfloat162float(hi.y));
                    size_t off = (size_t)(row0 + half * 8) * N + col;
                    *(__nv_bfloat162*)(Ch + off) = hi;
                    *(__nv_bfloat162*)(Cl + off) = lo;
                }
            } else {
                *(float2*)(C + (size_t)row0 * N + col)       = make_float2(c[mt][nt][0], c[mt][nt][1]);
                *(float2*)(C + (size_t)(row0 + 8) * N + col) = make_float2(c[mt][nt][2], c[mt][nt][3]);
            }
        }
    }
}

// ---------------------------------------------------------------------------
// V transpose: [B,S,D] bf16 (per head [s][hd]) -> [B,H,HD,S]
// ---------------------------------------------------------------------------
__global__ __launch_bounds__(256) void transpose_v(
    const __nv_bfloat16* __restrict__ vh, const __nv_bfloat16* __restrict__ vl,
    __nv_bfloat16* __restrict__ vth, __nv_bfloat16* __restrict__ vtl)
{
    __shared__ __nv_bfloat16 th[64 * 72];
    __shared__ __nv_bfloat16 tl[64 * 72];
    const int tid = threadIdx.x;
    const int bh = blockIdx.y;
    const int b = bh >> 4, h = bh & 15;
    const int s0 = blockIdx.x * 64;

    const size_t src = (size_t)(b * Sq + s0) * Dq + h * HDq;
    #pragma unroll
    for (int i = 0; i < 2; i++) {
        int chunk = i * 256 + tid;
        int r = chunk >> 3, cc = chunk & 7;
        *(uint4*)&th[r * 72 + cc * 8] = *(const uint4*)(vh + src + (size_t)r * Dq + cc * 8);
        *(uint4*)&tl[r * 72 + cc * 8] = *(const uint4*)(vl + src + (size_t)r * Dq + cc * 8);
    }
    __syncthreads();

    const size_t dst = (size_t)bh * HDq * Sq + s0;
    #pragma unroll
    for (int i = 0; i < 2; i++) {
        int chunk = i * 256 + tid;
        int r = chunk >> 3, cc = chunk & 7;     // r = hd, cc = s-octet
        alignas(16) __nv_bfloat16 tmpH[8];
        alignas(16) __nv_bfloat16 tmpL[8];
        #pragma unroll
        for (int e = 0; e < 8; e++) {
            tmpH[e] = th[(cc * 8 + e) * 72 + r];
            tmpL[e] = tl[(cc * 8 + e) * 72 + r];
        }
        *(uint4*)(vth + dst + (size_t)r * Sq + cc * 8) = *(uint4*)tmpH;
        *(uint4*)(vtl + dst + (size_t)r * Sq + cc * 8) = *(uint4*)tmpL;
    }
}

// ---------------------------------------------------------------------------
// Mask pack: uint32 [B,S,S] -> bit-packed [B,S,S/32]
// ---------------------------------------------------------------------------
__global__ __launch_bounds__(256) void pack_mask(
    const unsigned int* __restrict__ mask, unsigned int* __restrict__ mbits)
{
    int w = blockIdx.x * 256 + threadIdx.x;       // word index
    size_t row = (size_t)(w >> 6);
    int wi = w & 63;
    const uint4* p = (const uint4*)(mask + row * Sq + wi * 32);
    unsigned int bits = 0;
    #pragma unroll
    for (int i = 0; i < 8; i++) {
        uint4 m = p[i];
        bits |= (unsigned)(m.x != 0u) << (4 * i + 0);
        bits |= (unsigned)(m.y != 0u) << (4 * i + 1);
        bits |= (unsigned)(m.z != 0u) << (4 * i + 2);
        bits |= (unsigned)(m.w != 0u) << (4 * i + 3);
    }
    mbits[w] = bits;
}

// ---------------------------------------------------------------------------
// Tensor-core flash attention with cp.async double-buffered K/Vt tiles.
// Block = 128 q-rows of one (b,h); warp = 16 q-rows. All operands pre-split
// bf16 hi/lo in global; no conversions in-kernel. Mask pre-packed to bits.
// smem: 2 stages x (Kh|Kl|Vth|Vtl), each 64x72 bf16. Q staged in stage0 area.
// ---------------------------------------------------------------------------
#define APB    144                    // pitch bytes (72 bf16)
#define REG9   9216                   // 64*APB
#define STAGEB (4 * REG9)             // 36864
#define ATTN_SMEM (2 * STAGEB)        // 73728

__global__ __launch_bounds__(256, 2) void attn_tc(
    const __nv_bfloat16* __restrict__ Qhg, const __nv_bfloat16* __restrict__ Qlg,
    const __nv_bfloat16* __restrict__ Khg, const __nv_bfloat16* __restrict__ Klg,
    const __nv_bfloat16* __restrict__ Vthg, const __nv_bfloat16* __restrict__ Vtlg,
    const unsigned int* __restrict__ mbits, float* __restrict__ O)
{
    extern __shared__ char smem[];
    const uint32_t sbase = (uint32_t)__cvta_generic_to_shared(smem);

    const int tid  = threadIdx.x;
    const int wid  = tid >> 5;
    const int lane = tid & 31;
    const int lm   = lane >> 3;
    const int lr   = lane & 7;
    const int g    = lane >> 2;
    const int t2   = lane & 3;

    const int bh = blockIdx.y;
    const int b  = bh >> 4;
    const int h  = bh & 15;
    const int q0 = blockIdx.x * 128;

    // ---- stage Q hi/lo into smem (stage0 area), extract fragments ----
    const size_t qrow0 = (size_t)(b * Sq + q0) * Dq + h * HDq;
    #pragma unroll
    for (int i = 0; i < 4; i++) {
        int chunk = i * 256 + tid;            // 0..1023
        int r = chunk >> 3, cc = chunk & 7;
        uint32_t so = sbase + r * APB + cc * 16;
        cpa16(so,         Qhg + qrow0 + (size_t)r * Dq + cc * 8);
        cpa16(so + 18432, Qlg + qrow0 + (size_t)r * Dq + cc * 8);
    }
    cpa_commit();
    cpa_wait<0>();
    __syncthreads();

    uint32_t qa_h[4][4], qa_l[4][4];
    {
        const int a_row = wid * 16 + lr + ((lm & 1) << 3);
        #pragma unroll
        for (int ks = 0; ks < 4; ks++) {
            uint32_t off = (uint32_t)(a_row * APB) + (uint32_t)(ks * 32 + ((lm >> 1) << 4));
            ldm_x4(qa_h[ks][0], qa_h[ks][1], qa_h[ks][2], qa_h[ks][3], sbase + off);
            ldm_x4(qa_l[ks][0], qa_l[ks][1], qa_l[ks][2], qa_l[ks][3], sbase + 18432 + off);
        }
    }
    __syncthreads();   // Q staging area free for stage buffers

    float o_acc[8][4];
    #pragma unroll
    for (int j = 0; j < 8; j++)
        #pragma unroll
        for (int r = 0; r < 4; r++) o_acc[j][r] = 0.f;
    float m0 = -1e30f, m1 = -1e30f, l0 = 0.f, l1 = 0.f;

    const size_t kbase  = (size_t)(b * Sq) * Dq + h * HDq;
    const size_t vtbase = (size_t)bh * HDq * Sq;
    const size_t mrow   = ((size_t)b * Sq + q0) * 64;
    const int r0 = wid * 16 + g;
    const int r1 = r0 + 8;

    // issue stage 0
    {
        const uint32_t sb = sbase;
        #pragma unroll
        for (int i = 0; i < 2; i++) {
            int chunk = i * 256 + tid;
            int r = chunk >> 3, cc = chunk & 7;
            uint32_t so = sb + r * APB + cc * 16;
            size_t kq = kbase + (size_t)r * Dq + cc * 8;
            size_t vq = vtbase + (size_t)r * Sq + cc * 8;
            cpa16(so,             Khg + kq);
            cpa16(so + REG9,      Klg + kq);
            cpa16(so + 2 * REG9,  Vthg + vq);
            cpa16(so + 3 * REG9,  Vtlg + vq);
        }
        cpa_commit();
    }

    for (int t = 0; t < Sq / 64; t++) {
        const int kb = t * 64;
        __syncthreads();                    // everyone done with buf[(t-1)&1]
        if (t + 1 < Sq / 64) {
            const uint32_t sb = sbase + (uint32_t)((t + 1) & 1) * STAGEB;
            const int kb2 = kb + 64;
            #pragma unroll
            for (int i = 0; i < 2; i++) {
                int chunk = i * 256 + tid;
                int r = chunk >> 3, cc = chunk & 7;
                uint32_t so = sb + r * APB + cc * 16;
                size_t kq = kbase + (size_t)(kb2 + r) * Dq + cc * 8;
                size_t vq = vtbase + (size_t)r * Sq + kb2 + cc * 8;
                cpa16(so,             Khg + kq);
                cpa16(so + REG9,      Klg + kq);
                cpa16(so + 2 * REG9,  Vthg + vq);
                cpa16(so + 3 * REG9,  Vtlg + vq);
            }
            cpa_commit();
            cpa_wait<1>();
        } else {
            cpa_wait<0>();
        }
        __syncthreads();                    // stage t visible to all

        const uint32_t kbuf = sbase + (uint32_t)(t & 1) * STAGEB;

        // prefetch mask bit-words (consumed after S-MMAs)
        const uint2 mwA = *(const uint2*)(mbits + mrow + (size_t)r0 * 64 + (kb >> 5));
        const uint2 mwB = *(const uint2*)(mbits + mrow + (size_t)r1 * 64 + (kb >> 5));

        // ---- S = Q @ K^T (3-pass) ----
        float s[8][4];
        #pragma unroll
        for (int j = 0; j < 8; j++)
            #pragma unroll
            for (int r = 0; r < 4; r++) s[j][r] = 0.f;

        #pragma unroll
        for (int ks = 0; ks < 4; ks++) {
            #pragma unroll
            for (int p2 = 0; p2 < 4; p2++) {
                int ntile = p2 * 2 + (lm >> 1);
                uint32_t off = (uint32_t)((ntile * 8 + lr) * APB)
                             + (uint32_t)(ks * 32 + ((lm & 1) << 4));
                uint32_t bh0, bh1, bh2, bh3, bl0, bl1, bl2, bl3;
                ldm_x4(bh0, bh1, bh2, bh3, kbuf + off);
                ldm_x4(bl0, bl1, bl2, bl3, kbuf + REG9 + off);
                int n0 = p2 * 2, n1 = p2 * 2 + 1;
                mma_bf16(s[n0][0], s[n0][1], s[n0][2], s[n0][3],
                         qa_h[ks][0], qa_h[ks][1], qa_h[ks][2], qa_h[ks][3], bh0, bh1);
                mma_bf16(s[n1][0], s[n1][1], s[n1][2], s[n1][3],
                         qa_h[ks][0], qa_h[ks][1], qa_h[ks][2], qa_h[ks][3], bh2, bh3);
                mma_bf16(s[n0][0], s[n0][1], s[n0][2], s[n0][3],
                         qa_h[ks][0], qa_h[ks][1], qa_h[ks][2], qa_h[ks][3], bl0, bl1);
                mma_bf16(s[n1][0], s[n1][1], s[n1][2], s[n1][3],
                         qa_h[ks][0], qa_h[ks][1], qa_h[ks][2], qa_h[ks][3], bl2, bl3);
                mma_bf16(s[n0][0], s[n0][1], s[n0][2], s[n0][3],
                         qa_l[ks][0], qa_l[ks][1], qa_l[ks][2], qa_l[ks][3], bh0, bh1);
                mma_bf16(s[n1][0], s[n1][1], s[n1][2], s[n1][3],
                         qa_l[ks][0], qa_l[ks][1], qa_l[ks][2], qa_l[ks][3], bh2, bh3);
            }
        }

        // ---- masked online softmax (warp-local) ----
        {
            unsigned int w0 = mwA.x, w1 = mwA.y;
            unsigned int x0 = mwB.x, x1 = mwB.y;
            float rmax0 = -1e30f, rmax1 = -1e30f;
            #pragma unroll
            for (int j = 0; j < 8; j++) {
                unsigned int wr0 = (j < 4) ? w0 : w1;
                unsigned int wr1 = (j < 4) ? x0 : x1;
                int sh = ((j & 3) * 8) + t2 * 2;
                bool k00 = (wr0 >> sh) & 1, k01 = (wr0 >> (sh + 1)) & 1;
                bool k10 = (wr1 >> sh) & 1, k11 = (wr1 >> (sh + 1)) & 1;
                s[j][0] = k00 ? s[j][0] * 0.125f : -1e30f;
                s[j][1] = k01 ? s[j][1] * 0.125f : -1e30f;
                s[j][2] = k10 ? s[j][2] * 0.125f : -1e30f;
                s[j][3] = k11 ? s[j][3] * 0.125f : -1e30f;
                rmax0 = fmaxf(rmax0, fmaxf(s[j][0], s[j][1]));
                rmax1 = fmaxf(rmax1, fmaxf(s[j][2], s[j][3]));
            }
            rmax0 = fmaxf(rmax0, __shfl_xor_sync(0xffffffffu, rmax0, 1));
            rmax0 = fmaxf(rmax0, __shfl_xor_sync(0xffffffffu, rmax0, 2));
            rmax1 = fmaxf(rmax1, __shfl_xor_sync(0xffffffffu, rmax1, 1));
            rmax1 = fmaxf(rmax1, __shfl_xor_sync(0xffffffffu, rmax1, 2));

            float mn0 = fmaxf(m0, rmax0);
            float mn1 = fmaxf(m1, rmax1);
            float rs0 = 0.f, rs1 = 0.f;
            #pragma unroll
            for (int j = 0; j < 8; j++) {
                s[j][0] = (s[j][0] > -1e29f) ? __expf(s[j][0] - mn0) : 0.f;
                s[j][1] = (s[j][1] > -1e29f) ? __expf(s[j][1] - mn0) : 0.f;
                s[j][2] = (s[j][2] > -1e29f) ? __expf(s[j][2] - mn1) : 0.f;
                s[j][3] = (s[j][3] > -1e29f) ? __expf(s[j][3] - mn1) : 0.f;
                rs0 += s[j][0] + s[j][1];
                rs1 += s[j][2] + s[j][3];
            }
            rs0 += __shfl_xor_sync(0xffffffffu, rs0, 1);
            rs0 += __shfl_xor_sync(0xffffffffu, rs0, 2);
            rs1 += __shfl_xor_sync(0xffffffffu, rs1, 1);
            rs1 += __shfl_xor_sync(0xffffffffu, rs1, 2);

            float al0 = __expf(m0 - mn0);
            float al1 = __expf(m1 - mn1);
            l0 = l0 * al0 + rs0; m0 = mn0;
            l1 = l1 * al1 + rs1; m1 = mn1;
            #pragma unroll
            for (int j = 0; j < 8; j++) {
                o_acc[j][0] *= al0; o_acc[j][1] *= al0;
                o_acc[j][2] *= al1; o_acc[j][3] *= al1;
            }
        }

        // ---- O += P @ V (3-pass) ----
        #pragma unroll
        for (int kk = 0; kk < 4; kk++) {
            int ja = 2 * kk, jb = 2 * kk + 1;
            uint32_t pah[4], pal[4];
            {
                uint32_t h0 = pack_bf16(s[ja][0], s[ja][1]);
                uint32_t h1 = pack_bf16(s[ja][2], s[ja][3]);
                uint32_t h2 = pack_bf16(s[jb][0], s[jb][1]);
                uint32_t h3 = pack_bf16(s[jb][2], s[jb][3]);
                pah[0] = h0; pah[1] = h1; pah[2] = h2; pah[3] = h3;
                __nv_bfloat162 u;
                u = *(__nv_bfloat162*)&h0;
                pal[0] = pack_bf16(s[ja][0] - __bfloat162float(u.x), s[ja][1] - __bfloat162float(u.y));
                u = *(__nv_bfloat162*)&h1;
                pal[1] = pack_bf16(s[ja][2] - __bfloat162float(u.x), s[ja][3] - __bfloat162float(u.y));
                u = *(__nv_bfloat162*)&h2;
                pal[2] = pack_bf16(s[jb][0] - __bfloat162float(u.x), s[jb][1] - __bfloat162float(u.y));
                u = *(__nv_bfloat162*)&h3;
                pal[3] = pack_bf16(s[jb][2] - __bfloat162float(u.x), s[jb][3] - __bfloat162float(u.y));
            }
            #pragma unroll
            for (int p2 = 0; p2 < 4; p2++) {
                int ntile = p2 * 2 + (lm >> 1);
                uint32_t off = (uint32_t)((ntile * 8 + lr) * APB)
                             + (uint32_t)(kk * 32 + ((lm & 1) << 4));
                uint32_t bh0, bh1, bh2, bh3, bl0, bl1, bl2, bl3;
                ldm_x4(bh0, bh1, bh2, bh3, kbuf + 2 * REG9 + off);
                ldm_x4(bl0, bl1, bl2, bl3, kbuf + 3 * REG9 + off);
                int n0 = p2 * 2, n1 = p2 * 2 + 1;
                mma_bf16(o_acc[n0][0], o_acc[n0][1], o_acc[n0][2], o_acc[n0][3],
                         pah[0], pah[1], pah[2], pah[3], bh0, bh1);
                mma_bf16(o_acc[n1][0], o_acc[n1][1], o_acc[n1][2], o_acc[n1][3],
                         pah[0], pah[1], pah[2], pah[3], bh2, bh3);
                mma_bf16(o_acc[n0][0], o_acc[n0][1], o_acc[n0][2], o_acc[n0][3],
                         pah[0], pah[1], pah[2], pah[3], bl0, bl1);
                mma_bf16(o_acc[n1][0], o_acc[n1][1], o_acc[n1][2], o_acc[n1][3],
                         pah[0], pah[1], pah[2], pah[3], bl2, bl3);
                mma_bf16(o_acc[n0][0], o_acc[n0][1], o_acc[n0][2], o_acc[n0][3],
                         pal[0], pal[1], pal[2], pal[3], bh0, bh1);
                mma_bf16(o_acc[n1][0], o_acc[n1][1], o_acc[n1][2], o_acc[n1][3],
                         pal[0], pal[1], pal[2], pal[3], bh2, bh3);
            }
        }
    }

    // ---- epilogue ----
    const float inv0 = l0 > 0.f ? 1.f / l0 : 0.f;
    const float inv1 = l1 > 0.f ? 1.f / l1 : 0.f;
    float* Og = O + (size_t)b * Sq * Dq + (size_t)h * HDq;
    const int row0 = q0 + wid * 16 + g;
    #pragma unroll
    for (int j = 0; j < 8; j++) {
        int col = j * 8 + t2 * 2;
        *(float2*)(Og + (size_t)row0 * Dq + col) =
            make_float2(o_acc[j][0] * inv0, o_acc[j][1] * inv0);
        *(float2*)(Og + (size_t)(row0 + 8) * Dq + col) =
            make_float2(o_acc[j][2] * inv1, o_acc[j][3] * inv1);
    }
}

// ---------------------------------------------------------------------------
// Launch
// ---------------------------------------------------------------------------
extern "C" void kernel_launch(void* const* d_in, const int* in_sizes, int n_in,
                              void* d_out, int out_size)
{
    const float* x  = (const float*)d_in[0];
    const unsigned int* mask = (const unsigned int*)d_in[1];
    const float* wq = (const float*)d_in[2];
    const float* wk = (const float*)d_in[3];
    const float* wv = (const float*)d_in[4];
    const float* wo = (const float*)d_in[5];
    float* out = (float*)d_out;

    __nv_bfloat16 *qh, *ql, *kh, *kl, *vh, *vl, *vth, *vtl;
    unsigned int* mbits;
    float* attn;
    cudaGetSymbolAddress((void**)&qh,  g_qh);
    cudaGetSymbolAddress((void**)&ql,  g_ql);
    cudaGetSymbolAddress((void**)&kh,  g_kh);
    cudaGetSymbolAddress((void**)&kl,  g_kl);
    cudaGetSymbolAddress((void**)&vh,  g_vh);
    cudaGetSymbolAddress((void**)&vl,  g_vl);
    cudaGetSymbolAddress((void**)&vth, g_vth);
    cudaGetSymbolAddress((void**)&vtl, g_vtl);
    cudaGetSymbolAddress((void**)&mbits, g_mbits);
    cudaGetSymbolAddress((void**)&attn,  g_attn);

    pack_mask<<<(Bq * Sq * (Sq / 32)) / 256, 256>>>(mask, mbits);

    dim3 gp(Dq / 128, Mq / 128);
    gemm_nt_tc<true><<<gp, 256>>>(x, wq, nullptr, qh, ql, Mq, Dq, Dq);
    gemm_nt_tc<true><<<gp, 256>>>(x, wk, nullptr, kh, kl, Mq, Dq, Dq);
    gemm_nt_tc<true><<<gp, 256>>>(x, wv, nullptr, vh, vl, Mq, Dq, Dq);

    transpose_v<<<dim3(Sq / 64, Bq * Hq), 256>>>(vh, vl, vth, vtl);

    cudaFuncSetAttribute(attn_tc, cudaFuncAttributeMaxDynamicSharedMemorySize, ATTN_SMEM);
    attn_tc<<<dim3(Sq / 128, Bq * Hq), 256, ATTN_SMEM>>>(qh, ql, kh, kl, vth, vtl, mbits, attn);

    gemm_nt_tc<false><<<gp, 256>>>(attn, wo, out, nullptr, nullptr, Mq, Dq, Dq);
}

// round 8
// speedup vs baseline: 5.2581x; 1.2781x over previous
#include <cuda_runtime.h>
#include <cuda_bf16.h>
#include <cstdint>
#include <cstddef>

// Problem constants
#define Bq  4
#define Sq  2048
#define Dq  1024
#define Hq  16
#define HDq 64
#define Mq  (Bq * Sq)   // 8192

// Scratch (all bf16 hi/lo split pairs)
__device__ __nv_bfloat16 g_xh[(size_t)Mq * Dq];
__device__ __nv_bfloat16 g_xl[(size_t)Mq * Dq];
__device__ __nv_bfloat16 g_wh[(size_t)4 * Dq * Dq];   // wq|wk|wv|wo
__device__ __nv_bfloat16 g_wl[(size_t)4 * Dq * Dq];
__device__ __nv_bfloat16 g_qh[(size_t)Mq * Dq];
__device__ __nv_bfloat16 g_ql[(size_t)Mq * Dq];
__device__ __nv_bfloat16 g_kh[(size_t)Mq * Dq];
__device__ __nv_bfloat16 g_kl[(size_t)Mq * Dq];
__device__ __nv_bfloat16 g_vh[(size_t)Mq * Dq];
__device__ __nv_bfloat16 g_vl[(size_t)Mq * Dq];
__device__ __nv_bfloat16 g_vth[(size_t)Mq * Dq];      // [B,H,HD,S]
__device__ __nv_bfloat16 g_vtl[(size_t)Mq * Dq];
__device__ __nv_bfloat16 g_oh[(size_t)Mq * Dq];       // attention out hi
__device__ __nv_bfloat16 g_ol[(size_t)Mq * Dq];       // attention out lo
__device__ unsigned int  g_mbits[(size_t)Bq * Sq * (Sq / 32)];

// ---------------------------------------------------------------------------
// helpers
// ---------------------------------------------------------------------------
__device__ __forceinline__ void mma_bf16(float& d0, float& d1, float& d2, float& d3,
                                         uint32_t a0, uint32_t a1, uint32_t a2, uint32_t a3,
                                         uint32_t b0, uint32_t b1)
{
    asm volatile(
        "mma.sync.aligned.m16n8k16.row.col.f32.bf16.bf16.f32 "
        "{%0,%1,%2,%3}, {%4,%5,%6,%7}, {%8,%9}, {%0,%1,%2,%3};"
        : "+f"(d0), "+f"(d1), "+f"(d2), "+f"(d3)
        : "r"(a0), "r"(a1), "r"(a2), "r"(a3), "r"(b0), "r"(b1));
}

__device__ __forceinline__ void ldm_x4(uint32_t& r0, uint32_t& r1, uint32_t& r2, uint32_t& r3,
                                       uint32_t addr)
{
    asm volatile("ldmatrix.sync.aligned.m8n8.x4.shared.b16 {%0,%1,%2,%3}, [%4];"
                 : "=r"(r0), "=r"(r1), "=r"(r2), "=r"(r3) : "r"(addr));
}

__device__ __forceinline__ uint32_t pack_bf16(float e0, float e1)
{
    __nv_bfloat162 t = __floats2bfloat162_rn(e0, e1);
    return *(uint32_t*)&t;
}

__device__ __forceinline__ void cpa16(uint32_t saddr, const void* gptr)
{
    asm volatile("cp.async.cg.shared.global [%0], [%1], 16;" :: "r"(saddr), "l"(gptr));
}
__device__ __forceinline__ void cpa_commit() { asm volatile("cp.async.commit_group;"); }
template<int N> __device__ __forceinline__ void cpa_wait()
{ asm volatile("cp.async.wait_group %0;" :: "n"(N) : "memory"); }

// ---------------------------------------------------------------------------
// fp32 -> bf16 hi/lo split (elementwise)
// ---------------------------------------------------------------------------
__global__ __launch_bounds__(256) void split_f32(
    const float4* __restrict__ in,
    __nv_bfloat162* __restrict__ hi, __nv_bfloat162* __restrict__ lo)
{
    size_t i = (size_t)blockIdx.x * 256 + threadIdx.x;
    float4 v = in[i];
    __nv_bfloat162 h0 = __floats2bfloat162_rn(v.x, v.y);
    __nv_bfloat162 h1 = __floats2bfloat162_rn(v.z, v.w);
    __nv_bfloat162 l0 = __floats2bfloat162_rn(v.x - __bfloat162float(h0.x),
                                              v.y - __bfloat162float(h0.y));
    __nv_bfloat162 l1 = __floats2bfloat162_rn(v.z - __bfloat162float(h1.x),
                                              v.w - __bfloat162float(h1.y));
    hi[i * 2]     = h0; hi[i * 2 + 1] = h1;
    lo[i * 2]     = l0; lo[i * 2 + 1] = l1;
}

// ---------------------------------------------------------------------------
// Tensor-core NT GEMM on pre-split bf16 hi/lo operands, cp.async double-buffer.
// C[M,N] = A @ W^T, 3-pass (AhBh + AhBl + AlBh). BM=BN=128, BK=32, 8 warps.
// ---------------------------------------------------------------------------
#define GP2B  80                      // row pitch bytes (40 bf16)
#define GAB   (128 * GP2B)            // 10240 bytes per operand array
#define GSTG  (4 * GAB)               // 40960 per stage
#define GEMM_SMEM (2 * GSTG)          // 81920

template<bool BF16OUT>
__global__ __launch_bounds__(256, 2) void gemm_nt_bf(
    const __nv_bfloat16* __restrict__ Ahg, const __nv_bfloat16* __restrict__ Alg,
    const __nv_bfloat16* __restrict__ Whg, const __nv_bfloat16* __restrict__ Wlg,
    float* __restrict__ C, __nv_bfloat16* __restrict__ Ch, __nv_bfloat16* __restrict__ Cl,
    int M, int N, int K)
{
    extern __shared__ char smg[];
    const uint32_t sbase = (uint32_t)__cvta_generic_to_shared(smg);

    const int tid  = threadIdx.x;
    const int wid  = tid >> 5;
    const int lane = tid & 31;
    const int wm = wid >> 2;
    const int wn = wid & 3;
    const int bm = blockIdx.y * 128;
    const int bn = blockIdx.x * 128;
    const int lm  = lane >> 3;
    const int lr  = lane & 7;

    float c[4][4][4];
    #pragma unroll
    for (int i = 0; i < 4; i++)
        #pragma unroll
        for (int j = 0; j < 4; j++)
            #pragma unroll
            for (int r = 0; r < 4; r++) c[i][j][r] = 0.f;

    // stage issue: 512 16B-chunks per operand array, 2 per thread per array
    auto issue = [&](int k0, int stg) {
        const uint32_t sb = sbase + (uint32_t)stg * GSTG;
        #pragma unroll
        for (int i = 0; i < 2; i++) {
            int ch  = i * 256 + tid;        // 0..511
            int row = ch >> 2;              // 0..127
            int c16 = ch & 3;               // 16B unit (8 bf16)
            uint32_t so = sb + row * GP2B + c16 * 16;
            size_t ga = (size_t)(bm + row) * K + k0 + c16 * 8;
            size_t gw = (size_t)(bn + row) * K + k0 + c16 * 8;
            cpa16(so,            Ahg + ga);
            cpa16(so + GAB,      Alg + ga);
            cpa16(so + 2 * GAB,  Whg + gw);
            cpa16(so + 3 * GAB,  Wlg + gw);
        }
        cpa_commit();
    };

    issue(0, 0);
    const int T = K / 32;
    for (int t = 0; t < T; t++) {
        if (t + 1 < T) { issue((t + 1) * 32, (t + 1) & 1); cpa_wait<1>(); }
        else           { cpa_wait<0>(); }
        __syncthreads();                     // stage t visible to all

        const uint32_t sb = sbase + (uint32_t)(t & 1) * GSTG;

        #pragma unroll
        for (int ks = 0; ks < 2; ks++) {
            const int a_row_in16 = lr + ((lm & 1) << 3);
            const int a_kbyte    = ks * 32 + ((lm >> 1) << 4);

            uint32_t a_hi[4][4], a_lo[4][4];
            #pragma unroll
            for (int mt = 0; mt < 4; mt++) {
                uint32_t off = (uint32_t)((wm * 64 + mt * 16 + a_row_in16) * GP2B) + a_kbyte;
                ldm_x4(a_hi[mt][0], a_hi[mt][1], a_hi[mt][2], a_hi[mt][3], sb + off);
                ldm_x4(a_lo[mt][0], a_lo[mt][1], a_lo[mt][2], a_lo[mt][3], sb + GAB + off);
            }

            uint32_t b_hi[4][2], b_lo[4][2];
            #pragma unroll
            for (int p = 0; p < 2; p++) {
                int ntile = p * 2 + (lm >> 1);
                int n_row = wn * 32 + ntile * 8 + lr;
                uint32_t off = (uint32_t)(n_row * GP2B) + (uint32_t)(ks * 32 + ((lm & 1) << 4));
                uint32_t r0, r1, r2, r3;
                ldm_x4(r0, r1, r2, r3, sb + 2 * GAB + off);
                b_hi[p * 2 + 0][0] = r0; b_hi[p * 2 + 0][1] = r1;
                b_hi[p * 2 + 1][0] = r2; b_hi[p * 2 + 1][1] = r3;
                ldm_x4(r0, r1, r2, r3, sb + 3 * GAB + off);
                b_lo[p * 2 + 0][0] = r0; b_lo[p * 2 + 0][1] = r1;
                b_lo[p * 2 + 1][0] = r2; b_lo[p * 2 + 1][1] = r3;
            }

            #pragma unroll
            for (int mt = 0; mt < 4; mt++)
                #pragma unroll
                for (int nt = 0; nt < 4; nt++) {
                    mma_bf16(c[mt][nt][0], c[mt][nt][1], c[mt][nt][2], c[mt][nt][3],
                             a_hi[mt][0], a_hi[mt][1], a_hi[mt][2], a_hi[mt][3],
                             b_hi[nt][0], b_hi[nt][1]);
                    mma_bf16(c[mt][nt][0], c[mt][nt][1], c[mt][nt][2], c[mt][nt][3],
                             a_hi[mt][0], a_hi[mt][1], a_hi[mt][2], a_hi[mt][3],
                             b_lo[nt][0], b_lo[nt][1]);
                    mma_bf16(c[mt][nt][0], c[mt][nt][1], c[mt][nt][2], c[mt][nt][3],
                             a_lo[mt][0], a_lo[mt][1], a_lo[mt][2], a_lo[mt][3],
                             b_hi[nt][0], b_hi[nt][1]);
                }
        }
        __syncthreads();                     // done with buffer before reuse
    }

    const int g  = lane >> 2;
    const int t2 = lane & 3;
    #pragma unroll
    for (int mt = 0; mt < 4; mt++) {
        #pragma unroll
        for (int nt = 0; nt < 4; nt++) {
            int row0 = bm + wm * 64 + mt * 16 + g;
            int col  = bn + wn * 32 + nt * 8 + t2 * 2;
            if (BF16OUT) {
                #pragma unroll
                for (int half = 0; half < 2; half++) {
                    float v0 = c[mt][nt][half * 2], v1 = c[mt][nt][half * 2 + 1];
                    __nv_bfloat162 hi = __floats2bfloat162_rn(v0, v1);
                    __nv_bfloat162 lo = __floats2bfloat162_rn(v0 - __bfloat162float(hi.x),
                                                              v1 - __bfloat162float(hi.y));
                    size_t off = (size_t)(row0 + half * 8) * N + col;
                    *(__nv_bfloat162*)(Ch + off) = hi;
                    *(__nv_bfloat162*)(Cl + off) = lo;
                }
            } else {
                *(float2*)(C + (size_t)row0 * N + col)       = make_float2(c[mt][nt][0], c[mt][nt][1]);
                *(float2*)(C + (size_t)(row0 + 8) * N + col) = make_float2(c[mt][nt][2], c[mt][nt][3]);
            }
        }
    }
}

// ---------------------------------------------------------------------------
// V transpose: [B,S,D] bf16 (per head [s][hd]) -> [B,H,HD,S]
// ---------------------------------------------------------------------------
__global__ __launch_bounds__(256) void transpose_v(
    const __nv_bfloat16* __restrict__ vh, const __nv_bfloat16* __restrict__ vl,
    __nv_bfloat16* __restrict__ vth, __nv_bfloat16* __restrict__ vtl)
{
    __shared__ __nv_bfloat16 th[64 * 72];
    __shared__ __nv_bfloat16 tl[64 * 72];
    const int tid = threadIdx.x;
    const int bh = blockIdx.y;
    const int b = bh >> 4, h = bh & 15;
    const int s0 = blockIdx.x * 64;

    const size_t src = (size_t)(b * Sq + s0) * Dq + h * HDq;
    #pragma unroll
    for (int i = 0; i < 2; i++) {
        int chunk = i * 256 + tid;
        int r = chunk >> 3, cc = chunk & 7;
        *(uint4*)&th[r * 72 + cc * 8] = *(const uint4*)(vh + src + (size_t)r * Dq + cc * 8);
        *(uint4*)&tl[r * 72 + cc * 8] = *(const uint4*)(vl + src + (size_t)r * Dq + cc * 8);
    }
    __syncthreads();

    const size_t dst = (size_t)bh * HDq * Sq + s0;
    #pragma unroll
    for (int i = 0; i < 2; i++) {
        int chunk = i * 256 + tid;
        int r = chunk >> 3, cc = chunk & 7;
        alignas(16) __nv_bfloat16 tmpH[8];
        alignas(16) __nv_bfloat16 tmpL[8];
        #pragma unroll
        for (int e = 0; e < 8; e++) {
            tmpH[e] = th[(cc * 8 + e) * 72 + r];
            tmpL[e] = tl[(cc * 8 + e) * 72 + r];
        }
        *(uint4*)(vth + dst + (size_t)r * Sq + cc * 8) = *(uint4*)tmpH;
        *(uint4*)(vtl + dst + (size_t)r * Sq + cc * 8) = *(uint4*)tmpL;
    }
}

// ---------------------------------------------------------------------------
// Mask pack: uint32 [B,S,S] -> bit-packed [B,S,S/32]
// ---------------------------------------------------------------------------
__global__ __launch_bounds__(256) void pack_mask(
    const unsigned int* __restrict__ mask, unsigned int* __restrict__ mbits)
{
    int w = blockIdx.x * 256 + threadIdx.x;
    size_t row = (size_t)(w >> 6);
    int wi = w & 63;
    const uint4* p = (const uint4*)(mask + row * Sq + wi * 32);
    unsigned int bits = 0;
    #pragma unroll
    for (int i = 0; i < 8; i++) {
        uint4 m = p[i];
        bits |= (unsigned)(m.x != 0u) << (4 * i + 0);
        bits |= (unsigned)(m.y != 0u) << (4 * i + 1);
        bits |= (unsigned)(m.z != 0u) << (4 * i + 2);
        bits |= (unsigned)(m.w != 0u) << (4 * i + 3);
    }
    mbits[w] = bits;
}

// ---------------------------------------------------------------------------
// Tensor-core flash attention, cp.async double-buffered, bf16 hi/lo output.
// ---------------------------------------------------------------------------
#define APB    144
#define REG9   9216
#define STAGEB (4 * REG9)
#define ATTN_SMEM (2 * STAGEB)

__global__ __launch_bounds__(256, 2) void attn_tc(
    const __nv_bfloat16* __restrict__ Qhg, const __nv_bfloat16* __restrict__ Qlg,
    const __nv_bfloat16* __restrict__ Khg, const __nv_bfloat16* __restrict__ Klg,
    const __nv_bfloat16* __restrict__ Vthg, const __nv_bfloat16* __restrict__ Vtlg,
    const unsigned int* __restrict__ mbits,
    __nv_bfloat16* __restrict__ Ohg, __nv_bfloat16* __restrict__ Olg)
{
    extern __shared__ char smem[];
    const uint32_t sbase = (uint32_t)__cvta_generic_to_shared(smem);

    const int tid  = threadIdx.x;
    const int wid  = tid >> 5;
    const int lane = tid & 31;
    const int lm   = lane >> 3;
    const int lr   = lane & 7;
    const int g    = lane >> 2;
    const int t2   = lane & 3;

    const int bh = blockIdx.y;
    const int b  = bh >> 4;
    const int h  = bh & 15;
    const int q0 = blockIdx.x * 128;

    const size_t qrow0 = (size_t)(b * Sq + q0) * Dq + h * HDq;
    #pragma unroll
    for (int i = 0; i < 4; i++) {
        int chunk = i * 256 + tid;
        int r = chunk >> 3, cc = chunk & 7;
        uint32_t so = sbase + r * APB + cc * 16;
        cpa16(so,         Qhg + qrow0 + (size_t)r * Dq + cc * 8);
        cpa16(so + 18432, Qlg + qrow0 + (size_t)r * Dq + cc * 8);
    }
    cpa_commit();
    cpa_wait<0>();
    __syncthreads();

    uint32_t qa_h[4][4], qa_l[4][4];
    {
        const int a_row = wid * 16 + lr + ((lm & 1) << 3);
        #pragma unroll
        for (int ks = 0; ks < 4; ks++) {
            uint32_t off = (uint32_t)(a_row * APB) + (uint32_t)(ks * 32 + ((lm >> 1) << 4));
            ldm_x4(qa_h[ks][0], qa_h[ks][1], qa_h[ks][2], qa_h[ks][3], sbase + off);
            ldm_x4(qa_l[ks][0], qa_l[ks][1], qa_l[ks][2], qa_l[ks][3], sbase + 18432 + off);
        }
    }
    __syncthreads();

    float o_acc[8][4];
    #pragma unroll
    for (int j = 0; j < 8; j++)
        #pragma unroll
        for (int r = 0; r < 4; r++) o_acc[j][r] = 0.f;
    float m0 = -1e30f, m1 = -1e30f, l0 = 0.f, l1 = 0.f;

    const size_t kbase  = (size_t)(b * Sq) * Dq + h * HDq;
    const size_t vtbase = (size_t)bh * HDq * Sq;
    const size_t mrow   = ((size_t)b * Sq + q0) * 64;
    const int r0 = wid * 16 + g;
    const int r1 = r0 + 8;

    {
        const uint32_t sb = sbase;
        #pragma unroll
        for (int i = 0; i < 2; i++) {
            int chunk = i * 256 + tid;
            int r = chunk >> 3, cc = chunk & 7;
            uint32_t so = sb + r * APB + cc * 16;
            size_t kq = kbase + (size_t)r * Dq + cc * 8;
            size_t vq = vtbase + (size_t)r * Sq + cc * 8;
            cpa16(so,             Khg + kq);
            cpa16(so + REG9,      Klg + kq);
            cpa16(so + 2 * REG9,  Vthg + vq);
            cpa16(so + 3 * REG9,  Vtlg + vq);
        }
        cpa_commit();
    }

    for (int t = 0; t < Sq / 64; t++) {
        const int kb = t * 64;
        __syncthreads();
        if (t + 1 < Sq / 64) {
            const uint32_t sb = sbase + (uint32_t)((t + 1) & 1) * STAGEB;
            const int kb2 = kb + 64;
            #pragma unroll
            for (int i = 0; i < 2; i++) {
                int chunk = i * 256 + tid;
                int r = chunk >> 3, cc = chunk & 7;
                uint32_t so = sb + r * APB + cc * 16;
                size_t kq = kbase + (size_t)(kb2 + r) * Dq + cc * 8;
                size_t vq = vtbase + (size_t)r * Sq + kb2 + cc * 8;
                cpa16(so,             Khg + kq);
                cpa16(so + REG9,      Klg + kq);
                cpa16(so + 2 * REG9,  Vthg + vq);
                cpa16(so + 3 * REG9,  Vtlg + vq);
            }
            cpa_commit();
            cpa_wait<1>();
        } else {
            cpa_wait<0>();
        }
        __syncthreads();

        const uint32_t kbuf = sbase + (uint32_t)(t & 1) * STAGEB;

        const uint2 mwA = *(const uint2*)(mbits + mrow + (size_t)r0 * 64 + (kb >> 5));
        const uint2 mwB = *(const uint2*)(mbits + mrow + (size_t)r1 * 64 + (kb >> 5));

        float s[8][4];
        #pragma unroll
        for (int j = 0; j < 8; j++)
            #pragma unroll
            for (int r = 0; r < 4; r++) s[j][r] = 0.f;

        #pragma unroll
        for (int ks = 0; ks < 4; ks++) {
            #pragma unroll
            for (int p2 = 0; p2 < 4; p2++) {
                int ntile = p2 * 2 + (lm >> 1);
                uint32_t off = (uint32_t)((ntile * 8 + lr) * APB)
                             + (uint32_t)(ks * 32 + ((lm & 1) << 4));
                uint32_t bh0, bh1, bh2, bh3, bl0, bl1, bl2, bl3;
                ldm_x4(bh0, bh1, bh2, bh3, kbuf + off);
                ldm_x4(bl0, bl1, bl2, bl3, kbuf + REG9 + off);
                int n0 = p2 * 2, n1 = p2 * 2 + 1;
                mma_bf16(s[n0][0], s[n0][1], s[n0][2], s[n0][3],
                         qa_h[ks][0], qa_h[ks][1], qa_h[ks][2], qa_h[ks][3], bh0, bh1);
                mma_bf16(s[n1][0], s[n1][1], s[n1][2], s[n1][3],
                         qa_h[ks][0], qa_h[ks][1], qa_h[ks][2], qa_h[ks][3], bh2, bh3);
                mma_bf16(s[n0][0], s[n0][1], s[n0][2], s[n0][3],
                         qa_h[ks][0], qa_h[ks][1], qa_h[ks][2], qa_h[ks][3], bl0, bl1);
                mma_bf16(s[n1][0], s[n1][1], s[n1][2], s[n1][3],
                         qa_h[ks][0], qa_h[ks][1], qa_h[ks][2], qa_h[ks][3], bl2, bl3);
                mma_bf16(s[n0][0], s[n0][1], s[n0][2], s[n0][3],
                         qa_l[ks][0], qa_l[ks][1], qa_l[ks][2], qa_l[ks][3], bh0, bh1);
                mma_bf16(s[n1][0], s[n1][1], s[n1][2], s[n1][3],
                         qa_l[ks][0], qa_l[ks][1], qa_l[ks][2], qa_l[ks][3], bh2, bh3);
            }
        }

        {
            unsigned int w0 = mwA.x, w1 = mwA.y;
            unsigned int x0 = mwB.x, x1 = mwB.y;
            float rmax0 = -1e30f, rmax1 = -1e30f;
            #pragma unroll
            for (int j = 0; j < 8; j++) {
                unsigned int wr0 = (j < 4) ? w0 : w1;
                unsigned int wr1 = (j < 4) ? x0 : x1;
                int sh = ((j & 3) * 8) + t2 * 2;
                bool k00 = (wr0 >> sh) & 1, k01 = (wr0 >> (sh + 1)) & 1;
                bool k10 = (wr1 >> sh) & 1, k11 = (wr1 >> (sh + 1)) & 1;
                s[j][0] = k00 ? s[j][0] * 0.125f : -1e30f;
                s[j][1] = k01 ? s[j][1] * 0.125f : -1e30f;
                s[j][2] = k10 ? s[j][2] * 0.125f : -1e30f;
                s[j][3] = k11 ? s[j][3] * 0.125f : -1e30f;
                rmax0 = fmaxf(rmax0, fmaxf(s[j][0], s[j][1]));
                rmax1 = fmaxf(rmax1, fmaxf(s[j][2], s[j][3]));
            }
            rmax0 = fmaxf(rmax0, __shfl_xor_sync(0xffffffffu, rmax0, 1));
            rmax0 = fmaxf(rmax0, __shfl_xor_sync(0xffffffffu, rmax0, 2));
            rmax1 = fmaxf(rmax1, __shfl_xor_sync(0xffffffffu, rmax1, 1));
            rmax1 = fmaxf(rmax1, __shfl_xor_sync(0xffffffffu, rmax1, 2));

            float mn0 = fmaxf(m0, rmax0);
            float mn1 = fmaxf(m1, rmax1);
            float rs0 = 0.f, rs1 = 0.f;
            #pragma unroll
            for (int j = 0; j < 8; j++) {
                s[j][0] = (s[j][0] > -1e29f) ? __expf(s[j][0] - mn0) : 0.f;
                s[j][1] = (s[j][1] > -1e29f) ? __expf(s[j][1] - mn0) : 0.f;
                s[j][2] = (s[j][2] > -1e29f) ? __expf(s[j][2] - mn1) : 0.f;
                s[j][3] = (s[j][3] > -1e29f) ? __expf(s[j][3] - mn1) : 0.f;
                rs0 += s[j][0] + s[j][1];
                rs1 += s[j][2] + s[j][3];
            }
            rs0 += __shfl_xor_sync(0xffffffffu, rs0, 1);
            rs0 += __shfl_xor_sync(0xffffffffu, rs0, 2);
            rs1 += __shfl_xor_sync(0xffffffffu, rs1, 1);
            rs1 += __shfl_xor_sync(0xffffffffu, rs1, 2);

            float al0 = __expf(m0 - mn0);
            float al1 = __expf(m1 - mn1);
            l0 = l0 * al0 + rs0; m0 = mn0;
            l1 = l1 * al1 + rs1; m1 = mn1;
            #pragma unroll
            for (int j = 0; j < 8; j++) {
                o_acc[j][0] *= al0; o_acc[j][1] *= al0;
                o_acc[j][2] *= al1; o_acc[j][3] *= al1;
            }
        }

        #pragma unroll
        for (int kk = 0; kk < 4; kk++) {
            int ja = 2 * kk, jb = 2 * kk + 1;
            uint32_t pah[4], pal[4];
            {
                uint32_t h0 = pack_bf16(s[ja][0], s[ja][1]);
                uint32_t h1 = pack_bf16(s[ja][2], s[ja][3]);
                uint32_t h2 = pack_bf16(s[jb][0], s[jb][1]);
                uint32_t h3 = pack_bf16(s[jb][2], s[jb][3]);
                pah[0] = h0; pah[1] = h1; pah[2] = h2; pah[3] = h3;
                __nv_bfloat162 u;
                u = *(__nv_bfloat162*)&h0;
                pal[0] = pack_bf16(s[ja][0] - __bfloat162float(u.x), s[ja][1] - __bfloat162float(u.y));
                u = *(__nv_bfloat162*)&h1;
                pal[1] = pack_bf16(s[ja][2] - __bfloat162float(u.x), s[ja][3] - __bfloat162float(u.y));
                u = *(__nv_bfloat162*)&h2;
                pal[2] = pack_bf16(s[jb][0] - __bfloat162float(u.x), s[jb][1] - __bfloat162float(u.y));
                u = *(__nv_bfloat162*)&h3;
                pal[3] = pack_bf16(s[jb][2] - __bfloat162float(u.x), s[jb][3] - __bfloat162float(u.y));
            }
            #pragma unroll
            for (int p2 = 0; p2 < 4; p2++) {
                int ntile = p2 * 2 + (lm >> 1);
                uint32_t off = (uint32_t)((ntile * 8 + lr) * APB)
                             + (uint32_t)(kk * 32 + ((lm & 1) << 4));
                uint32_t bh0, bh1, bh2, bh3, bl0, bl1, bl2, bl3;
                ldm_x4(bh0, bh1, bh2, bh3, kbuf + 2 * REG9 + off);
                ldm_x4(bl0, bl1, bl2, bl3, kbuf + 3 * REG9 + off);
                int n0 = p2 * 2, n1 = p2 * 2 + 1;
                mma_bf16(o_acc[n0][0], o_acc[n0][1], o_acc[n0][2], o_acc[n0][3],
                         pah[0], pah[1], pah[2], pah[3], bh0, bh1);
                mma_bf16(o_acc[n1][0], o_acc[n1][1], o_acc[n1][2], o_acc[n1][3],
                         pah[0], pah[1], pah[2], pah[3], bh2, bh3);
                mma_bf16(o_acc[n0][0], o_acc[n0][1], o_acc[n0][2], o_acc[n0][3],
                         pah[0], pah[1], pah[2], pah[3], bl0, bl1);
                mma_bf16(o_acc[n1][0], o_acc[n1][1], o_acc[n1][2], o_acc[n1][3],
                         pah[0], pah[1], pah[2], pah[3], bl2, bl3);
                mma_bf16(o_acc[n0][0], o_acc[n0][1], o_acc[n0][2], o_acc[n0][3],
                         pal[0], pal[1], pal[2], pal[3], bh0, bh1);
                mma_bf16(o_acc[n1][0], o_acc[n1][1], o_acc[n1][2], o_acc[n1][3],
                         pal[0], pal[1], pal[2], pal[3], bh2, bh3);
            }
        }
    }

    // epilogue: normalize, split to bf16 hi/lo, store
    const float inv0 = l0 > 0.f ? 1.f / l0 : 0.f;
    const float inv1 = l1 > 0.f ? 1.f / l1 : 0.f;
    const size_t obase = (size_t)b * Sq * Dq + (size_t)h * HDq;
    const int row0 = q0 + wid * 16 + g;
    #pragma unroll
    for (int j = 0; j < 8; j++) {
        int col = j * 8 + t2 * 2;
        #pragma unroll
        for (int half = 0; half < 2; half++) {
            float v0 = (half ? o_acc[j][2] * inv1 : o_acc[j][0] * inv0);
            float v1 = (half ? o_acc[j][3] * inv1 : o_acc[j][1] * inv0);
            __nv_bfloat162 hv = __floats2bfloat162_rn(v0, v1);
            __nv_bfloat162 lv = __floats2bfloat162_rn(v0 - __bfloat162float(hv.x),
                                                      v1 - __bfloat162float(hv.y));
            size_t off = obase + (size_t)(row0 + half * 8) * Dq + col;
            *(__nv_bfloat162*)(Ohg + off) = hv;
            *(__nv_bfloat162*)(Olg + off) = lv;
        }
    }
}

// ---------------------------------------------------------------------------
// Launch
// ---------------------------------------------------------------------------
extern "C" void kernel_launch(void* const* d_in, const int* in_sizes, int n_in,
                              void* d_out, int out_size)
{
    const float* x  = (const float*)d_in[0];
    const unsigned int* mask = (const unsigned int*)d_in[1];
    const float* wq = (const float*)d_in[2];
    const float* wk = (const float*)d_in[3];
    const float* wv = (const float*)d_in[4];
    const float* wo = (const float*)d_in[5];
    float* out = (float*)d_out;

    __nv_bfloat16 *xh, *xl, *wh, *wl, *qh, *ql, *kh, *kl, *vh, *vl, *vth, *vtl, *oh, *ol;
    unsigned int* mbits;
    cudaGetSymbolAddress((void**)&xh,  g_xh);
    cudaGetSymbolAddress((void**)&xl,  g_xl);
    cudaGetSymbolAddress((void**)&wh,  g_wh);
    cudaGetSymbolAddress((void**)&wl,  g_wl);
    cudaGetSymbolAddress((void**)&qh,  g_qh);
    cudaGetSymbolAddress((void**)&ql,  g_ql);
    cudaGetSymbolAddress((void**)&kh,  g_kh);
    cudaGetSymbolAddress((void**)&kl,  g_kl);
    cudaGetSymbolAddress((void**)&vh,  g_vh);
    cudaGetSymbolAddress((void**)&vl,  g_vl);
    cudaGetSymbolAddress((void**)&vth, g_vth);
    cudaGetSymbolAddress((void**)&vtl, g_vtl);
    cudaGetSymbolAddress((void**)&oh,  g_oh);
    cudaGetSymbolAddress((void**)&ol,  g_ol);
    cudaGetSymbolAddress((void**)&mbits, g_mbits);

    const size_t WSZ = (size_t)Dq * Dq;

    pack_mask<<<(Bq * Sq * (Sq / 32)) / 256, 256>>>(mask, mbits);
    split_f32<<<(Mq * Dq) / 1024, 256>>>((const float4*)x,
                                         (__nv_bfloat162*)xh, (__nv_bfloat162*)xl);
    split_f32<<<(Dq * Dq) / 1024, 256>>>((const float4*)wq,
                                         (__nv_bfloat162*)(wh + 0 * WSZ), (__nv_bfloat162*)(wl + 0 * WSZ));
    split_f32<<<(Dq * Dq) / 1024, 256>>>((const float4*)wk,
                                         (__nv_bfloat162*)(wh + 1 * WSZ), (__nv_bfloat162*)(wl + 1 * WSZ));
    split_f32<<<(Dq * Dq) / 1024, 256>>>((const float4*)wv,
                                         (__nv_bfloat162*)(wh + 2 * WSZ), (__nv_bfloat162*)(wl + 2 * WSZ));
    split_f32<<<(Dq * Dq) / 1024, 256>>>((const float4*)wo,
                                         (__nv_bfloat162*)(wh + 3 * WSZ), (__nv_bfloat162*)(wl + 3 * WSZ));

    dim3 gp(Dq / 128, Mq / 128);
    cudaFuncSetAttribute(gemm_nt_bf<true>,  cudaFuncAttributeMaxDynamicSharedMemorySize, GEMM_SMEM);
    cudaFuncSetAttribute(gemm_nt_bf<false>, cudaFuncAttributeMaxDynamicSharedMemorySize, GEMM_SMEM);

    gemm_nt_bf<true><<<gp, 256, GEMM_SMEM>>>(xh, xl, wh + 0 * WSZ, wl + 0 * WSZ,
                                             nullptr, qh, ql, Mq, Dq, Dq);
    gemm_nt_bf<true><<<gp, 256, GEMM_SMEM>>>(xh, xl, wh + 1 * WSZ, wl + 1 * WSZ,
                                             nullptr, kh, kl, Mq, Dq, Dq);
    gemm_nt_bf<true><<<gp, 256, GEMM_SMEM>>>(xh, xl, wh + 2 * WSZ, wl + 2 * WSZ,
                                             nullptr, vh, vl, Mq, Dq, Dq);

    transpose_v<<<dim3(Sq / 64, Bq * Hq), 256>>>(vh, vl, vth, vtl);

    cudaFuncSetAttribute(attn_tc, cudaFuncAttributeMaxDynamicSharedMemorySize, ATTN_SMEM);
    attn_tc<<<dim3(Sq / 128, Bq * Hq), 256, ATTN_SMEM>>>(qh, ql, kh, kl, vth, vtl, mbits, oh, ol);

    gemm_nt_bf<false><<<gp, 256, GEMM_SMEM>>>(oh, ol, wh + 3 * WSZ, wl + 3 * WSZ,
                                              out, nullptr, nullptr, Mq, Dq, Dq);
}